// round 8
// baseline (speedup 1.0000x reference)
#include <cuda_runtime.h>
#include <cuda_bf16.h>
#include <cstdint>

#define N_NODES 100000
#define N_EDGES 640000
#define D 128
#define SCAN_BS 1024
#define N_SCAN_BLOCKS ((N_NODES + SCAN_BS - 1) / SCAN_BS)  // 98
#define M_TILE 64
#define GEMM_BLOCKS ((N_NODES + M_TILE - 1) / M_TILE)      // 1563

// ---- scratch ----
__device__ float g_h[(size_t)N_NODES * D];
__device__ float g_h2[(size_t)N_NODES * D];
__device__ int   g_deg[N_NODES];
__device__ float g_dinv[N_NODES];
__device__ int   g_rowptr[N_NODES + 1];
__device__ int   g_cursor[N_NODES];
__device__ int   g_bsum[128];
__device__ int   g_boff[128];
__device__ int   g_esrc[N_EDGES];
__device__ float g_enorm[N_EDGES];
__device__ int   g_ei[2 * N_EDGES];
__device__ unsigned char g_wt[3 * 2 * 32768];

__device__ __forceinline__ uint32_t swz(int row, int kb) {
    return (uint32_t)(row * 256 + (kb ^ ((row & 7) << 4)));
}

__device__ __forceinline__ uint32_t s2u(const void* p) {
    uint32_t a;
    asm("{ .reg .u64 t; cvta.to.shared.u64 t, %1; cvt.u32.u64 %0, t; }"
        : "=r"(a) : "l"(p));
    return a;
}

#define LDSM_X4(d, a) \
    asm volatile("ldmatrix.sync.aligned.m8n8.x4.shared.b16 {%0,%1,%2,%3}, [%4];" \
        : "=r"((d)[0]), "=r"((d)[1]), "=r"((d)[2]), "=r"((d)[3]) : "r"(a))

#define MMA_BF16(c, a, b0, b1) \
    asm volatile("mma.sync.aligned.m16n8k16.row.col.f32.bf16.bf16.f32 " \
        "{%0,%1,%2,%3}, {%4,%5,%6,%7}, {%8,%9}, {%0,%1,%2,%3};" \
        : "+f"((c)[0]), "+f"((c)[1]), "+f"((c)[2]), "+f"((c)[3]) \
        : "r"((a)[0]), "r"((a)[1]), "r"((a)[2]), "r"((a)[3]), "r"(b0), "r"(b1))

#define CP_ASYNC16(dst, src) \
    asm volatile("cp.async.ca.shared.global [%0], [%1], 16;" :: "r"(dst), "l"(src))
#define CP_COMMIT() asm volatile("cp.async.commit_group;")
#define CP_WAIT0()  asm volatile("cp.async.wait_group 0;")

// ---------------- edge-index dtype sniff ----------------
__device__ __forceinline__ bool ei_is_int64(const int* __restrict__ w) {
    bool z = true;
#pragma unroll
    for (int i = 1; i < 32; i += 2) z &= (w[i] == 0);
    return z;
}

__global__ void k_convert_hist(const int* __restrict__ ei_raw, int* __restrict__ ei32,
                               int* __restrict__ deg) {
    int e = blockIdx.x * blockDim.x + threadIdx.x;
    if (e >= N_EDGES) return;
    bool is64 = ei_is_int64(ei_raw);
    int r = is64 ? ei_raw[2 * e] : ei_raw[e];
    int c = is64 ? ei_raw[2 * (N_EDGES + e)] : ei_raw[N_EDGES + e];
    ei32[e] = r;
    ei32[N_EDGES + e] = c;
    atomicAdd(&deg[c], 1);
}

// ---------------- W prep ----------------
__global__ void k_wprep(const float* __restrict__ W) {
    int i = blockIdx.x * blockDim.x + threadIdx.x;
    if (i >= 3 * 128 * 128) return;
    int l = i >> 14;
    int rem = i & 16383;
    int k = rem >> 7;
    int n = rem & 127;
    float w = W[l * 16384 + k * 128 + n];
    __nv_bfloat16 hb = __float2bfloat16_rn(w);
    float hf = __bfloat162float(hb);
    __nv_bfloat16 lb = __float2bfloat16_rn(w - hf);
    uint32_t pos = swz(n, k * 2);
    *(__nv_bfloat16*)(g_wt + (size_t)(l * 2 + 0) * 32768 + pos) = hb;
    *(__nv_bfloat16*)(g_wt + (size_t)(l * 2 + 1) * 32768 + pos) = lb;
}

// ---------------- prep ----------------
__global__ void k_zeroi(int* __restrict__ p, int n) {
    int i = blockIdx.x * blockDim.x + threadIdx.x;
    if (i < n) p[i] = 0;
}

__global__ __launch_bounds__(256) void k_dinv_bsum(const int* __restrict__ deg,
                                                   float* __restrict__ dinv,
                                                   int* __restrict__ bsum) {
    __shared__ int s[256];
    int b = blockIdx.x, t = threadIdx.x;
    int base = b * SCAN_BS + t * 4;
    int v = 0;
#pragma unroll
    for (int j = 0; j < 4; j++) {
        int i = base + j;
        if (i < N_NODES) {
            int d = deg[i];
            dinv[i] = (d > 0) ? rsqrtf((float)d) : 0.f;
            v += d;
        }
    }
    s[t] = v;
    __syncthreads();
    for (int off = 128; off > 0; off >>= 1) {
        if (t < off) s[t] += s[t + off];
        __syncthreads();
    }
    if (t == 0) bsum[b] = s[0];
}

__global__ __launch_bounds__(128) void k_scansums(const int* __restrict__ bsum,
                                                  int* __restrict__ boff,
                                                  int* __restrict__ rowptr) {
    __shared__ int s[128];
    int t = threadIdx.x;
    int v = (t < N_SCAN_BLOCKS) ? bsum[t] : 0;
    s[t] = v;
    __syncthreads();
    for (int off = 1; off < 128; off <<= 1) {
        int u = (t >= off) ? s[t - off] : 0;
        __syncthreads();
        s[t] += u;
        __syncthreads();
    }
    if (t < N_SCAN_BLOCKS) boff[t] = s[t] - v;
    if (t == N_SCAN_BLOCKS - 1) rowptr[N_NODES] = s[t];
}

__global__ __launch_bounds__(SCAN_BS) void k_scanapply(const int* __restrict__ deg,
                                                       const int* __restrict__ boff,
                                                       int* __restrict__ rowptr,
                                                       int* __restrict__ cursor) {
    __shared__ int s[SCAN_BS];
    int b = blockIdx.x, t = threadIdx.x;
    int i = b * SCAN_BS + t;
    int v = (i < N_NODES) ? deg[i] : 0;
    s[t] = v;
    __syncthreads();
    for (int off = 1; off < SCAN_BS; off <<= 1) {
        int u = (t >= off) ? s[t - off] : 0;
        __syncthreads();
        s[t] += u;
        __syncthreads();
    }
    if (i < N_NODES) {
        int excl = boff[b] + s[t] - v;
        rowptr[i] = excl;
        cursor[i] = excl;
    }
}

__global__ void k_fill(const int* __restrict__ ei, const float* __restrict__ dinv,
                       int* __restrict__ cursor, int* __restrict__ esrc,
                       float* __restrict__ enorm) {
    int e = blockIdx.x * blockDim.x + threadIdx.x;
    if (e >= N_EDGES) return;
    int r = ei[e];
    int c = ei[N_EDGES + e];
    int pos = atomicAdd(&cursor[c], 1);
    esrc[pos] = r;
    enorm[pos] = dinv[r] * dinv[c];
}

// ---------------- shared GEMM pieces (R6 proven shape: 8 warps, m32n32) ----------------
#define OFF_AH 0u
#define OFF_AL 16384u
#define OFF_WH 32768u
#define OFF_WL 65536u
#define GEMM_SMEM 98304
#define GEMM_TPB 256

__device__ __forceinline__ uint2 pack4(float x, float y, float z, float w) {
    __nv_bfloat162 p0 = __floats2bfloat162_rn(x, y);
    __nv_bfloat162 p1 = __floats2bfloat162_rn(z, w);
    return make_uint2(*(uint32_t*)&p0, *(uint32_t*)&p1);
}

__device__ __forceinline__ void split_store(unsigned char* smem, int r, int kb4,
                                            float4 v) {
    uint2 hi = pack4(v.x, v.y, v.z, v.w);
    float hx = __bfloat162float(__float2bfloat16_rn(v.x));
    float hy = __bfloat162float(__float2bfloat16_rn(v.y));
    float hz = __bfloat162float(__float2bfloat16_rn(v.z));
    float hw = __bfloat162float(__float2bfloat16_rn(v.w));
    uint2 lo = pack4(v.x - hx, v.y - hy, v.z - hz, v.w - hw);
    uint32_t addr = swz(r, kb4);
    *(uint2*)(smem + OFF_AH + addr) = hi;
    *(uint2*)(smem + OFF_AL + addr) = lo;
}

__device__ __forceinline__ void w_copy_async(uint32_t sb, int tid, int layer) {
    const unsigned char* sh = g_wt + (size_t)(layer * 2 + 0) * 32768;
    const unsigned char* sl = g_wt + (size_t)(layer * 2 + 1) * 32768;
#pragma unroll
    for (int j = 0; j < 8; j++) {
        uint32_t off = (uint32_t)(tid + j * 256) * 16;
        CP_ASYNC16(sb + OFF_WH + off, sh + off);
        CP_ASYNC16(sb + OFF_WL + off, sl + off);
    }
    CP_COMMIT();
}

// mainloop + epilogue (identical math to R6)
__device__ __forceinline__ void mma_main_epi(uint32_t sb, unsigned char* smem,
                                             int tid, int row0,
                                             float* __restrict__ H) {
    const int w = tid >> 5;
    const int lane = tid & 31;
    const int wm = w >> 2;
    const int wn = w & 3;

    float acc[2][4][4];
#pragma unroll
    for (int mi = 0; mi < 2; mi++)
#pragma unroll
        for (int ni = 0; ni < 4; ni++)
#pragma unroll
            for (int j = 0; j < 4; j++) acc[mi][ni][j] = 0.f;

    const int a_row = wm * 32 + (lane & 15);
    const int a_kb  = (lane >> 4) << 4;
    const int b_row = wn * 32 + ((lane >> 4) << 3) + (lane & 7);
    const int b_kb  = ((lane >> 3) & 1) << 4;

#pragma unroll
    for (int ks = 0; ks < 8; ks++) {
        uint32_t ah[2][4], al[2][4], bh[2][4], bl[2][4];
#pragma unroll
        for (int mi = 0; mi < 2; mi++) {
            uint32_t addr = swz(a_row + mi * 16, a_kb + ks * 32);
            LDSM_X4(ah[mi], sb + OFF_AH + addr);
            LDSM_X4(al[mi], sb + OFF_AL + addr);
        }
#pragma unroll
        for (int p = 0; p < 2; p++) {
            uint32_t addr = swz(b_row + p * 16, b_kb + ks * 32);
            LDSM_X4(bh[p], sb + OFF_WH + addr);
            LDSM_X4(bl[p], sb + OFF_WL + addr);
        }
#pragma unroll
        for (int mi = 0; mi < 2; mi++) {
#pragma unroll
            for (int p = 0; p < 2; p++) {
#pragma unroll
                for (int s = 0; s < 2; s++) {
                    int ni = p * 2 + s;
                    MMA_BF16(acc[mi][ni], ah[mi], bh[p][s * 2], bh[p][s * 2 + 1]);
                    MMA_BF16(acc[mi][ni], ah[mi], bl[p][s * 2], bl[p][s * 2 + 1]);
                    MMA_BF16(acc[mi][ni], al[mi], bh[p][s * 2], bh[p][s * 2 + 1]);
                }
            }
        }
    }

#pragma unroll
    for (int mi = 0; mi < 2; mi++) {
        int r1 = row0 + wm * 32 + mi * 16 + (lane >> 2);
        int r2 = r1 + 8;
#pragma unroll
        for (int ni = 0; ni < 4; ni++) {
            int col = wn * 32 + ni * 8 + 2 * (lane & 3);
            if (r1 < N_NODES)
                *(float2*)(H + (size_t)r1 * D + col) = make_float2(acc[mi][ni][0], acc[mi][ni][1]);
            if (r2 < N_NODES)
                *(float2*)(H + (size_t)r2 * D + col) = make_float2(acc[mi][ni][2], acc[mi][ni][3]);
        }
    }
}

// ---------------- dense GEMM (layer 0): H = X @ W0 ----------------
__global__ __launch_bounds__(GEMM_TPB, 2) void k_gemm0(const float* __restrict__ X,
                                                       float* __restrict__ H) {
    extern __shared__ unsigned char smem[];
    const uint32_t sb = s2u(smem);
    const int tid = threadIdx.x;
    const int row0 = blockIdx.x * M_TILE;

    w_copy_async(sb, tid, 0);

    {
        int r = tid >> 2;
        int q = tid & 3;
        int gr = row0 + r;
        bool valid = gr < N_NODES;
        const float4* src = (const float4*)(X + (size_t)gr * D);
#pragma unroll
        for (int j = 0; j < 8; j++) {
            int qp = q + j * 4;
            float4 v = valid ? src[qp] : make_float4(0.f, 0.f, 0.f, 0.f);
            split_store(smem, r, qp * 8, v);
        }
    }
    CP_WAIT0();
    __syncthreads();
    mma_main_epi(sb, smem, tid, row0, H);
}

// ---------------- fused layer: H_out = (gather(H_in)+b -> relu) @ W_layer ----------------
// Staging: warp-per-row CSR gather (8 rows per warp), fused bias+relu+split.
__global__ __launch_bounds__(GEMM_TPB, 2) void k_fused(const int* __restrict__ rowptr,
                                                       const int* __restrict__ esrc,
                                                       const float* __restrict__ enorm,
                                                       const float* __restrict__ Hin,
                                                       const float* __restrict__ bvec,
                                                       int layer,
                                                       float* __restrict__ Hout) {
    extern __shared__ unsigned char smem[];
    const uint32_t sb = s2u(smem);
    const int tid = threadIdx.x;
    const int w = tid >> 5;
    const int lane = tid & 31;
    const int row0 = blockIdx.x * M_TILE;

    w_copy_async(sb, tid, layer);

    // ---- staging = CSR gather + bias + relu + split, 8 rows per warp ----
    float4 bv = ((const float4*)bvec)[lane];
#pragma unroll
    for (int i = 0; i < 8; i++) {
        int r = w * 8 + i;
        int gr = row0 + r;
        float4 acc = bv;
        if (gr < N_NODES) {
            int e = rowptr[gr];
            int end = rowptr[gr + 1];
            for (; e + 4 <= end; e += 4) {
                int s0 = esrc[e], s1 = esrc[e + 1], s2 = esrc[e + 2], s3 = esrc[e + 3];
                float n0 = enorm[e], n1 = enorm[e + 1], n2 = enorm[e + 2], n3 = enorm[e + 3];
                float4 v0 = __ldg(&((const float4*)(Hin + (size_t)s0 * D))[lane]);
                float4 v1 = __ldg(&((const float4*)(Hin + (size_t)s1 * D))[lane]);
                float4 v2 = __ldg(&((const float4*)(Hin + (size_t)s2 * D))[lane]);
                float4 v3 = __ldg(&((const float4*)(Hin + (size_t)s3 * D))[lane]);
                acc.x += v0.x * n0 + v1.x * n1 + v2.x * n2 + v3.x * n3;
                acc.y += v0.y * n0 + v1.y * n1 + v2.y * n2 + v3.y * n3;
                acc.z += v0.z * n0 + v1.z * n1 + v2.z * n2 + v3.z * n3;
                acc.w += v0.w * n0 + v1.w * n1 + v2.w * n2 + v3.w * n3;
            }
            for (; e < end; e++) {
                int s0 = esrc[e];
                float n0 = enorm[e];
                float4 v0 = __ldg(&((const float4*)(Hin + (size_t)s0 * D))[lane]);
                acc.x += v0.x * n0; acc.y += v0.y * n0;
                acc.z += v0.z * n0; acc.w += v0.w * n0;
            }
        }
        // relu (fused layers always have relu before the GEMM)
        acc.x = fmaxf(acc.x, 0.f); acc.y = fmaxf(acc.y, 0.f);
        acc.z = fmaxf(acc.z, 0.f); acc.w = fmaxf(acc.w, 0.f);
        split_store(smem, r, lane * 8, acc);
    }
    CP_WAIT0();
    __syncthreads();
    mma_main_epi(sb, smem, tid, row0, Hout);
}

// ---------------- final CSR gather: out = gather(H)+b ----------------
__global__ __launch_bounds__(256) void k_gather(const int* __restrict__ rowptr,
                                                const int* __restrict__ esrc,
                                                const float* __restrict__ enorm,
                                                const float* __restrict__ H,
                                                const float* __restrict__ bvec,
                                                float* __restrict__ out) {
    int n = blockIdx.x * 8 + (threadIdx.x >> 5);
    if (n >= N_NODES) return;
    int lane = threadIdx.x & 31;

    float4 acc = ((const float4*)bvec)[lane];

    int e = rowptr[n];
    int end = rowptr[n + 1];
    for (; e + 4 <= end; e += 4) {
        int s0 = esrc[e], s1 = esrc[e + 1], s2 = esrc[e + 2], s3 = esrc[e + 3];
        float n0 = enorm[e], n1 = enorm[e + 1], n2 = enorm[e + 2], n3 = enorm[e + 3];
        float4 v0 = __ldg(&((const float4*)(H + (size_t)s0 * D))[lane]);
        float4 v1 = __ldg(&((const float4*)(H + (size_t)s1 * D))[lane]);
        float4 v2 = __ldg(&((const float4*)(H + (size_t)s2 * D))[lane]);
        float4 v3 = __ldg(&((const float4*)(H + (size_t)s3 * D))[lane]);
        acc.x += v0.x * n0 + v1.x * n1 + v2.x * n2 + v3.x * n3;
        acc.y += v0.y * n0 + v1.y * n1 + v2.y * n2 + v3.y * n3;
        acc.z += v0.z * n0 + v1.z * n1 + v2.z * n2 + v3.z * n3;
        acc.w += v0.w * n0 + v1.w * n1 + v2.w * n2 + v3.w * n3;
    }
    for (; e < end; e++) {
        int s0 = esrc[e];
        float n0 = enorm[e];
        float4 v0 = __ldg(&((const float4*)(H + (size_t)s0 * D))[lane]);
        acc.x += v0.x * n0; acc.y += v0.y * n0;
        acc.z += v0.z * n0; acc.w += v0.w * n0;
    }
    ((float4*)(out + (size_t)n * D))[lane] = acc;
}

// ---------------- launch ----------------
extern "C" void kernel_launch(void* const* d_in, const int* in_sizes, int n_in,
                              void* d_out, int out_size) {
    const float* x = (const float*)d_in[0];
    const int* ei_raw = (const int*)d_in[1];
    const float* W = (const float*)d_in[3];
    const float* b = (const float*)d_in[4];
    float* out = (float*)d_out;

    float *dinv, *h, *h2, *enorm;
    int *deg, *rowptr, *cursor, *bsum, *boff, *esrc, *ei;
    cudaGetSymbolAddress((void**)&dinv, g_dinv);
    cudaGetSymbolAddress((void**)&h, g_h);
    cudaGetSymbolAddress((void**)&h2, g_h2);
    cudaGetSymbolAddress((void**)&enorm, g_enorm);
    cudaGetSymbolAddress((void**)&deg, g_deg);
    cudaGetSymbolAddress((void**)&rowptr, g_rowptr);
    cudaGetSymbolAddress((void**)&cursor, g_cursor);
    cudaGetSymbolAddress((void**)&bsum, g_bsum);
    cudaGetSymbolAddress((void**)&boff, g_boff);
    cudaGetSymbolAddress((void**)&esrc, g_esrc);
    cudaGetSymbolAddress((void**)&ei, g_ei);

    cudaFuncSetAttribute(k_gemm0, cudaFuncAttributeMaxDynamicSharedMemorySize, GEMM_SMEM);
    cudaFuncSetAttribute(k_fused, cudaFuncAttributeMaxDynamicSharedMemorySize, GEMM_SMEM);

    const int TPB = 256;
    const int GATH_BLOCKS = (N_NODES + 7) / 8;

    // fork: gemm0 (+wprep) overlaps the edge-prep chain
    cudaStream_t s2;
    cudaEvent_t evFork, evJoin;
    cudaStreamCreateWithFlags(&s2, cudaStreamNonBlocking);
    cudaEventCreateWithFlags(&evFork, cudaEventDisableTiming);
    cudaEventCreateWithFlags(&evJoin, cudaEventDisableTiming);

    cudaEventRecord(evFork, 0);
    cudaStreamWaitEvent(s2, evFork, 0);

    k_wprep<<<(3 * 128 * 128 + TPB - 1) / TPB, TPB, 0, s2>>>(W);
    k_gemm0<<<GEMM_BLOCKS, GEMM_TPB, GEMM_SMEM, s2>>>(x, h);
    cudaEventRecord(evJoin, s2);

    k_zeroi<<<(N_NODES + TPB - 1) / TPB, TPB>>>(deg, N_NODES);
    k_convert_hist<<<(N_EDGES + TPB - 1) / TPB, TPB>>>(ei_raw, ei, deg);
    k_dinv_bsum<<<N_SCAN_BLOCKS, 256>>>(deg, dinv, bsum);
    k_scansums<<<1, 128>>>(bsum, boff, rowptr);
    k_scanapply<<<N_SCAN_BLOCKS, SCAN_BS>>>(deg, boff, rowptr, cursor);
    k_fill<<<(N_EDGES + TPB - 1) / TPB, TPB>>>(ei, dinv, cursor, esrc, enorm);

    cudaStreamWaitEvent(0, evJoin, 0);

    // fused layers: gather+bias+relu+GEMM in one kernel
    k_fused<<<GEMM_BLOCKS, GEMM_TPB, GEMM_SMEM>>>(rowptr, esrc, enorm, h, b + 0 * D, 1, h2);
    k_fused<<<GEMM_BLOCKS, GEMM_TPB, GEMM_SMEM>>>(rowptr, esrc, enorm, h2, b + 1 * D, 2, h);
    // final gather + bias (no trailing GEMM/relu)
    k_gather<<<GATH_BLOCKS, TPB>>>(rowptr, esrc, enorm, h, b + 2 * D, out);
}

// round 9
// speedup vs baseline: 1.1831x; 1.1831x over previous
#include <cuda_runtime.h>
#include <cuda_bf16.h>
#include <cstdint>

#define N_NODES 100000
#define N_EDGES 640000
#define D 128
#define SCAN_BS 1024
#define N_SCAN_BLOCKS ((N_NODES + SCAN_BS - 1) / SCAN_BS)  // 98
#define M_TILE 64
#define GEMM_BLOCKS ((N_NODES + M_TILE - 1) / M_TILE)      // 1563

// split-half pipeline geometry
#define GEMM_BLK_A 782                 // rows [0, 50048)
#define GEMM_BLK_B (GEMM_BLOCKS - GEMM_BLK_A)  // 781
#define NODE_SPLIT (GEMM_BLK_A * M_TILE)       // 50048
#define GATH_BLK_A (NODE_SPLIT / 8)            // 6256
#define GATH_BLK_B ((N_NODES - NODE_SPLIT + 7) / 8)  // 6244

// ---- scratch ----
__device__ float g_h[(size_t)N_NODES * D];
__device__ float g_bufA[(size_t)N_NODES * D];
__device__ float g_bufB[(size_t)N_NODES * D];
__device__ int   g_deg[N_NODES];
__device__ float g_dinv[N_NODES];
__device__ int   g_rowptr[N_NODES + 1];
__device__ int   g_cursor[N_NODES];
__device__ int   g_bsum[128];
__device__ int   g_boff[128];
__device__ int   g_esrc[N_EDGES];
__device__ float g_enorm[N_EDGES];
__device__ int   g_ei[2 * N_EDGES];
__device__ unsigned char g_wt[3 * 2 * 32768];

__device__ __forceinline__ uint32_t swz(int row, int kb) {
    return (uint32_t)(row * 256 + (kb ^ ((row & 7) << 4)));
}

__device__ __forceinline__ uint32_t s2u(const void* p) {
    uint32_t a;
    asm("{ .reg .u64 t; cvta.to.shared.u64 t, %1; cvt.u32.u64 %0, t; }"
        : "=r"(a) : "l"(p));
    return a;
}

#define LDSM_X4(d, a) \
    asm volatile("ldmatrix.sync.aligned.m8n8.x4.shared.b16 {%0,%1,%2,%3}, [%4];" \
        : "=r"((d)[0]), "=r"((d)[1]), "=r"((d)[2]), "=r"((d)[3]) : "r"(a))

#define MMA_BF16(c, a, b0, b1) \
    asm volatile("mma.sync.aligned.m16n8k16.row.col.f32.bf16.bf16.f32 " \
        "{%0,%1,%2,%3}, {%4,%5,%6,%7}, {%8,%9}, {%0,%1,%2,%3};" \
        : "+f"((c)[0]), "+f"((c)[1]), "+f"((c)[2]), "+f"((c)[3]) \
        : "r"((a)[0]), "r"((a)[1]), "r"((a)[2]), "r"((a)[3]), "r"(b0), "r"(b1))

#define CP_ASYNC16(dst, src) \
    asm volatile("cp.async.ca.shared.global [%0], [%1], 16;" :: "r"(dst), "l"(src))
#define CP_COMMIT() asm volatile("cp.async.commit_group;")
#define CP_WAIT0()  asm volatile("cp.async.wait_group 0;")

// ---------------- edge-index dtype sniff ----------------
__device__ __forceinline__ bool ei_is_int64(const int* __restrict__ w) {
    bool z = true;
#pragma unroll
    for (int i = 1; i < 32; i += 2) z &= (w[i] == 0);
    return z;
}

__global__ void k_convert_hist(const int* __restrict__ ei_raw, int* __restrict__ ei32,
                               int* __restrict__ deg) {
    int e = blockIdx.x * blockDim.x + threadIdx.x;
    if (e >= N_EDGES) return;
    bool is64 = ei_is_int64(ei_raw);
    int r = is64 ? ei_raw[2 * e] : ei_raw[e];
    int c = is64 ? ei_raw[2 * (N_EDGES + e)] : ei_raw[N_EDGES + e];
    ei32[e] = r;
    ei32[N_EDGES + e] = c;
    atomicAdd(&deg[c], 1);
}

// ---------------- W prep ----------------
__global__ void k_wprep(const float* __restrict__ W) {
    int i = blockIdx.x * blockDim.x + threadIdx.x;
    if (i >= 3 * 128 * 128) return;
    int l = i >> 14;
    int rem = i & 16383;
    int k = rem >> 7;
    int n = rem & 127;
    float w = W[l * 16384 + k * 128 + n];
    __nv_bfloat16 hb = __float2bfloat16_rn(w);
    float hf = __bfloat162float(hb);
    __nv_bfloat16 lb = __float2bfloat16_rn(w - hf);
    uint32_t pos = swz(n, k * 2);
    *(__nv_bfloat16*)(g_wt + (size_t)(l * 2 + 0) * 32768 + pos) = hb;
    *(__nv_bfloat16*)(g_wt + (size_t)(l * 2 + 1) * 32768 + pos) = lb;
}

// ---------------- prep ----------------
__global__ void k_zeroi(int* __restrict__ p, int n) {
    int i = blockIdx.x * blockDim.x + threadIdx.x;
    if (i < n) p[i] = 0;
}

__global__ __launch_bounds__(256) void k_dinv_bsum(const int* __restrict__ deg,
                                                   float* __restrict__ dinv,
                                                   int* __restrict__ bsum) {
    __shared__ int s[256];
    int b = blockIdx.x, t = threadIdx.x;
    int base = b * SCAN_BS + t * 4;
    int v = 0;
#pragma unroll
    for (int j = 0; j < 4; j++) {
        int i = base + j;
        if (i < N_NODES) {
            int d = deg[i];
            dinv[i] = (d > 0) ? rsqrtf((float)d) : 0.f;
            v += d;
        }
    }
    s[t] = v;
    __syncthreads();
    for (int off = 128; off > 0; off >>= 1) {
        if (t < off) s[t] += s[t + off];
        __syncthreads();
    }
    if (t == 0) bsum[b] = s[0];
}

__global__ __launch_bounds__(128) void k_scansums(const int* __restrict__ bsum,
                                                  int* __restrict__ boff,
                                                  int* __restrict__ rowptr) {
    __shared__ int s[128];
    int t = threadIdx.x;
    int v = (t < N_SCAN_BLOCKS) ? bsum[t] : 0;
    s[t] = v;
    __syncthreads();
    for (int off = 1; off < 128; off <<= 1) {
        int u = (t >= off) ? s[t - off] : 0;
        __syncthreads();
        s[t] += u;
        __syncthreads();
    }
    if (t < N_SCAN_BLOCKS) boff[t] = s[t] - v;
    if (t == N_SCAN_BLOCKS - 1) rowptr[N_NODES] = s[t];
}

__global__ __launch_bounds__(SCAN_BS) void k_scanapply(const int* __restrict__ deg,
                                                       const int* __restrict__ boff,
                                                       int* __restrict__ rowptr,
                                                       int* __restrict__ cursor) {
    __shared__ int s[SCAN_BS];
    int b = blockIdx.x, t = threadIdx.x;
    int i = b * SCAN_BS + t;
    int v = (i < N_NODES) ? deg[i] : 0;
    s[t] = v;
    __syncthreads();
    for (int off = 1; off < SCAN_BS; off <<= 1) {
        int u = (t >= off) ? s[t - off] : 0;
        __syncthreads();
        s[t] += u;
        __syncthreads();
    }
    if (i < N_NODES) {
        int excl = boff[b] + s[t] - v;
        rowptr[i] = excl;
        cursor[i] = excl;
    }
}

__global__ void k_fill(const int* __restrict__ ei, const float* __restrict__ dinv,
                       int* __restrict__ cursor, int* __restrict__ esrc,
                       float* __restrict__ enorm) {
    int e = blockIdx.x * blockDim.x + threadIdx.x;
    if (e >= N_EDGES) return;
    int r = ei[e];
    int c = ei[N_EDGES + e];
    int pos = atomicAdd(&cursor[c], 1);
    esrc[pos] = r;
    enorm[pos] = dinv[r] * dinv[c];
}

// ---------------- GEMM (R6 proven: 256 thr, 8 warps 2m x 4n, m32n32) ----------------
#define OFF_AH 0u
#define OFF_AL 16384u
#define OFF_WH 32768u
#define OFF_WL 65536u
#define GEMM_SMEM 98304
#define GEMM_TPB 256

__device__ __forceinline__ uint2 pack4(float x, float y, float z, float w) {
    __nv_bfloat162 p0 = __floats2bfloat162_rn(x, y);
    __nv_bfloat162 p1 = __floats2bfloat162_rn(z, w);
    return make_uint2(*(uint32_t*)&p0, *(uint32_t*)&p1);
}

template <bool RELU>
__global__ __launch_bounds__(GEMM_TPB, 2) void k_gemm(const float* __restrict__ X,
                                                      int layer,
                                                      float* __restrict__ H,
                                                      int block_base) {
    extern __shared__ unsigned char smem[];
    const uint32_t sb = s2u(smem);
    const int tid = threadIdx.x;
    const int w = tid >> 5;
    const int lane = tid & 31;
    const int wm = w >> 2;
    const int wn = w & 3;
    const int row0 = (block_base + blockIdx.x) * M_TILE;

    {
        const unsigned char* sh = g_wt + (size_t)(layer * 2 + 0) * 32768;
        const unsigned char* sl = g_wt + (size_t)(layer * 2 + 1) * 32768;
#pragma unroll
        for (int j = 0; j < 8; j++) {
            uint32_t off = (uint32_t)(tid + j * 256) * 16;
            CP_ASYNC16(sb + OFF_WH + off, sh + off);
            CP_ASYNC16(sb + OFF_WL + off, sl + off);
        }
        CP_COMMIT();
    }

    {
        int r = tid >> 2;
        int q = tid & 3;
        int gr = row0 + r;
        bool valid = gr < N_NODES;
        const float4* src = (const float4*)(X + (size_t)gr * D);
#pragma unroll
        for (int j = 0; j < 8; j++) {
            int qp = q + j * 4;
            float4 v = valid ? src[qp] : make_float4(0.f, 0.f, 0.f, 0.f);
            if (RELU) {
                v.x = fmaxf(v.x, 0.f); v.y = fmaxf(v.y, 0.f);
                v.z = fmaxf(v.z, 0.f); v.w = fmaxf(v.w, 0.f);
            }
            uint2 hi = pack4(v.x, v.y, v.z, v.w);
            float hx = __bfloat162float(__float2bfloat16_rn(v.x));
            float hy = __bfloat162float(__float2bfloat16_rn(v.y));
            float hz = __bfloat162float(__float2bfloat16_rn(v.z));
            float hw = __bfloat162float(__float2bfloat16_rn(v.w));
            uint2 lo = pack4(v.x - hx, v.y - hy, v.z - hz, v.w - hw);
            uint32_t addr = swz(r, qp * 8);
            *(uint2*)(smem + OFF_AH + addr) = hi;
            *(uint2*)(smem + OFF_AL + addr) = lo;
        }
    }
    CP_WAIT0();
    __syncthreads();

    float acc[2][4][4];
#pragma unroll
    for (int mi = 0; mi < 2; mi++)
#pragma unroll
        for (int ni = 0; ni < 4; ni++)
#pragma unroll
            for (int j = 0; j < 4; j++) acc[mi][ni][j] = 0.f;

    const int a_row = wm * 32 + (lane & 15);
    const int a_kb  = (lane >> 4) << 4;
    const int b_row = wn * 32 + ((lane >> 4) << 3) + (lane & 7);
    const int b_kb  = ((lane >> 3) & 1) << 4;

#pragma unroll
    for (int ks = 0; ks < 8; ks++) {
        uint32_t ah[2][4], al[2][4], bh[2][4], bl[2][4];
#pragma unroll
        for (int mi = 0; mi < 2; mi++) {
            uint32_t addr = swz(a_row + mi * 16, a_kb + ks * 32);
            LDSM_X4(ah[mi], sb + OFF_AH + addr);
            LDSM_X4(al[mi], sb + OFF_AL + addr);
        }
#pragma unroll
        for (int p = 0; p < 2; p++) {
            uint32_t addr = swz(b_row + p * 16, b_kb + ks * 32);
            LDSM_X4(bh[p], sb + OFF_WH + addr);
            LDSM_X4(bl[p], sb + OFF_WL + addr);
        }
#pragma unroll
        for (int mi = 0; mi < 2; mi++) {
#pragma unroll
            for (int p = 0; p < 2; p++) {
#pragma unroll
                for (int s = 0; s < 2; s++) {
                    int ni = p * 2 + s;
                    MMA_BF16(acc[mi][ni], ah[mi], bh[p][s * 2], bh[p][s * 2 + 1]);
                    MMA_BF16(acc[mi][ni], ah[mi], bl[p][s * 2], bl[p][s * 2 + 1]);
                    MMA_BF16(acc[mi][ni], al[mi], bh[p][s * 2], bh[p][s * 2 + 1]);
                }
            }
        }
    }

#pragma unroll
    for (int mi = 0; mi < 2; mi++) {
        int r1 = row0 + wm * 32 + mi * 16 + (lane >> 2);
        int r2 = r1 + 8;
#pragma unroll
        for (int ni = 0; ni < 4; ni++) {
            int col = wn * 32 + ni * 8 + 2 * (lane & 3);
            if (r1 < N_NODES)
                *(float2*)(H + (size_t)r1 * D + col) = make_float2(acc[mi][ni][0], acc[mi][ni][1]);
            if (r2 < N_NODES)
                *(float2*)(H + (size_t)r2 * D + col) = make_float2(acc[mi][ni][2], acc[mi][ni][3]);
        }
    }
}

// ---------------- CSR gather ----------------
__global__ __launch_bounds__(256) void k_gather(const int* __restrict__ rowptr,
                                                const int* __restrict__ esrc,
                                                const float* __restrict__ enorm,
                                                const float* __restrict__ H,
                                                const float* __restrict__ bvec,
                                                float* __restrict__ out,
                                                int node_base) {
    int n = node_base + blockIdx.x * 8 + (threadIdx.x >> 5);
    if (n >= N_NODES) return;
    int lane = threadIdx.x & 31;

    float4 acc = ((const float4*)bvec)[lane];

    int e = rowptr[n];
    int end = rowptr[n + 1];
    for (; e + 4 <= end; e += 4) {
        int s0 = esrc[e], s1 = esrc[e + 1], s2 = esrc[e + 2], s3 = esrc[e + 3];
        float n0 = enorm[e], n1 = enorm[e + 1], n2 = enorm[e + 2], n3 = enorm[e + 3];
        float4 v0 = __ldg(&((const float4*)(H + (size_t)s0 * D))[lane]);
        float4 v1 = __ldg(&((const float4*)(H + (size_t)s1 * D))[lane]);
        float4 v2 = __ldg(&((const float4*)(H + (size_t)s2 * D))[lane]);
        float4 v3 = __ldg(&((const float4*)(H + (size_t)s3 * D))[lane]);
        acc.x += v0.x * n0 + v1.x * n1 + v2.x * n2 + v3.x * n3;
        acc.y += v0.y * n0 + v1.y * n1 + v2.y * n2 + v3.y * n3;
        acc.z += v0.z * n0 + v1.z * n1 + v2.z * n2 + v3.z * n3;
        acc.w += v0.w * n0 + v1.w * n1 + v2.w * n2 + v3.w * n3;
    }
    for (; e < end; e++) {
        int s0 = esrc[e];
        float n0 = enorm[e];
        float4 v0 = __ldg(&((const float4*)(H + (size_t)s0 * D))[lane]);
        acc.x += v0.x * n0; acc.y += v0.y * n0;
        acc.z += v0.z * n0; acc.w += v0.w * n0;
    }
    ((float4*)(out + (size_t)n * D))[lane] = acc;
}

// ---------------- launch: split-half pipelined schedule ----------------
extern "C" void kernel_launch(void* const* d_in, const int* in_sizes, int n_in,
                              void* d_out, int out_size) {
    const float* x = (const float*)d_in[0];
    const int* ei_raw = (const int*)d_in[1];
    const float* W = (const float*)d_in[3];
    const float* b = (const float*)d_in[4];
    float* out = (float*)d_out;

    float *dinv, *h, *bufA, *bufB, *enorm;
    int *deg, *rowptr, *cursor, *bsum, *boff, *esrc, *ei;
    cudaGetSymbolAddress((void**)&dinv, g_dinv);
    cudaGetSymbolAddress((void**)&h, g_h);
    cudaGetSymbolAddress((void**)&bufA, g_bufA);
    cudaGetSymbolAddress((void**)&bufB, g_bufB);
    cudaGetSymbolAddress((void**)&enorm, g_enorm);
    cudaGetSymbolAddress((void**)&deg, g_deg);
    cudaGetSymbolAddress((void**)&rowptr, g_rowptr);
    cudaGetSymbolAddress((void**)&cursor, g_cursor);
    cudaGetSymbolAddress((void**)&bsum, g_bsum);
    cudaGetSymbolAddress((void**)&boff, g_boff);
    cudaGetSymbolAddress((void**)&esrc, g_esrc);
    cudaGetSymbolAddress((void**)&ei, g_ei);

    cudaFuncSetAttribute(k_gemm<false>, cudaFuncAttributeMaxDynamicSharedMemorySize, GEMM_SMEM);
    cudaFuncSetAttribute(k_gemm<true>, cudaFuncAttributeMaxDynamicSharedMemorySize, GEMM_SMEM);

    const int TPB = 256;

    cudaStream_t s2;
    cudaStreamCreateWithFlags(&s2, cudaStreamNonBlocking);
    cudaEvent_t evFork, evJoin, evG0a, evM1a, evM1b, evG1a, evM2a, evM2b, evEnd;
    cudaEventCreateWithFlags(&evFork, cudaEventDisableTiming);
    cudaEventCreateWithFlags(&evJoin, cudaEventDisableTiming);
    cudaEventCreateWithFlags(&evG0a, cudaEventDisableTiming);
    cudaEventCreateWithFlags(&evM1a, cudaEventDisableTiming);
    cudaEventCreateWithFlags(&evM1b, cudaEventDisableTiming);
    cudaEventCreateWithFlags(&evG1a, cudaEventDisableTiming);
    cudaEventCreateWithFlags(&evM2a, cudaEventDisableTiming);
    cudaEventCreateWithFlags(&evM2b, cudaEventDisableTiming);
    cudaEventCreateWithFlags(&evEnd, cudaEventDisableTiming);

    // ---- head: fork gemm0 (+wprep) against the edge-prep chain ----
    cudaEventRecord(evFork, 0);
    cudaStreamWaitEvent(s2, evFork, 0);

    k_wprep<<<(3 * 128 * 128 + TPB - 1) / TPB, TPB, 0, s2>>>(W);
    k_gemm<false><<<GEMM_BLOCKS, GEMM_TPB, GEMM_SMEM, s2>>>(x, 0, h, 0);
    cudaEventRecord(evJoin, s2);

    k_zeroi<<<(N_NODES + TPB - 1) / TPB, TPB>>>(deg, N_NODES);
    k_convert_hist<<<(N_EDGES + TPB - 1) / TPB, TPB>>>(ei_raw, ei, deg);
    k_dinv_bsum<<<N_SCAN_BLOCKS, 256>>>(deg, dinv, bsum);
    k_scansums<<<1, 128>>>(bsum, boff, rowptr);
    k_scanapply<<<N_SCAN_BLOCKS, SCAN_BS>>>(deg, boff, rowptr, cursor);
    k_fill<<<(N_EDGES + TPB - 1) / TPB, TPB>>>(ei, dinv, cursor, esrc, enorm);

    cudaStreamWaitEvent(0, evJoin, 0);

    // ---- split-half pipeline ----
    // s0: G0a -> M1a -> [M1b] G1a -> M2a -> [M2b] G2a
    // s2: [G0a] G0b -> M1b -> [M1a,G1a] G1b -> M2b -> [M2a] G2b
    // layer 0->1 boundary
    k_gather<<<GATH_BLK_A, TPB>>>(rowptr, esrc, enorm, h, b + 0 * D, bufA, 0);
    cudaEventRecord(evG0a, 0);
    cudaStreamWaitEvent(s2, evG0a, 0);
    k_gather<<<GATH_BLK_B, TPB, 0, s2>>>(rowptr, esrc, enorm, h, b + 0 * D, bufA, NODE_SPLIT);

    k_gemm<true><<<GEMM_BLK_A, GEMM_TPB, GEMM_SMEM>>>(bufA, 1, bufB, 0);
    cudaEventRecord(evM1a, 0);
    k_gemm<true><<<GEMM_BLK_B, GEMM_TPB, GEMM_SMEM, s2>>>(bufA, 1, bufB, GEMM_BLK_A);
    cudaEventRecord(evM1b, s2);

    // layer 1->2 boundary (bufB = h1)
    cudaStreamWaitEvent(0, evM1b, 0);
    k_gather<<<GATH_BLK_A, TPB>>>(rowptr, esrc, enorm, bufB, b + 1 * D, bufA, 0);
    cudaEventRecord(evG1a, 0);
    cudaStreamWaitEvent(s2, evM1a, 0);
    cudaStreamWaitEvent(s2, evG1a, 0);
    k_gather<<<GATH_BLK_B, TPB, 0, s2>>>(rowptr, esrc, enorm, bufB, b + 1 * D, bufA, NODE_SPLIT);

    k_gemm<true><<<GEMM_BLK_A, GEMM_TPB, GEMM_SMEM>>>(bufA, 2, h, 0);
    cudaEventRecord(evM2a, 0);
    k_gemm<true><<<GEMM_BLK_B, GEMM_TPB, GEMM_SMEM, s2>>>(bufA, 2, h, GEMM_BLK_A);
    cudaEventRecord(evM2b, s2);

    // final gathers (h = h2) -> out, both halves concurrent
    cudaStreamWaitEvent(0, evM2b, 0);
    k_gather<<<GATH_BLK_A, TPB>>>(rowptr, esrc, enorm, h, b + 2 * D, out, 0);
    cudaStreamWaitEvent(s2, evM2a, 0);
    k_gather<<<GATH_BLK_B, TPB, 0, s2>>>(rowptr, esrc, enorm, h, b + 2 * D, out, NODE_SPLIT);
    cudaEventRecord(evEnd, s2);
    cudaStreamWaitEvent(0, evEnd, 0);
}

// round 10
// speedup vs baseline: 1.2380x; 1.0465x over previous
#include <cuda_runtime.h>
#include <cuda_bf16.h>
#include <cstdint>

#define N_NODES 100000
#define N_EDGES 640000
#define D 128
#define SCAN_BS 1024
#define N_SCAN_BLOCKS ((N_NODES + SCAN_BS - 1) / SCAN_BS)  // 98
#define M_TILE 64
#define GEMM_BLOCKS ((N_NODES + M_TILE - 1) / M_TILE)      // 1563

// ---- scratch ----
__device__ float g_h[(size_t)N_NODES * D];
__device__ float g_h2[(size_t)N_NODES * D];
// pre-split, pre-swizzled A-tile images (bf16): [tile][64 rows][256B]
__device__ unsigned char g_ahi[(size_t)GEMM_BLOCKS * 16384];
__device__ unsigned char g_alo[(size_t)GEMM_BLOCKS * 16384];
__device__ int   g_deg[N_NODES];
__device__ float g_dinv[N_NODES];
__device__ int   g_rowptr[N_NODES + 1];
__device__ int   g_cursor[N_NODES];
__device__ int   g_bsum[128];
__device__ int   g_boff[128];
__device__ int   g_esrc[N_EDGES];
__device__ float g_enorm[N_EDGES];
__device__ int   g_ei[2 * N_EDGES];
__device__ unsigned char g_wt[3 * 2 * 32768];

__device__ __forceinline__ uint32_t swz(int row, int kb) {
    return (uint32_t)(row * 256 + (kb ^ ((row & 7) << 4)));
}

__device__ __forceinline__ uint32_t s2u(const void* p) {
    uint32_t a;
    asm("{ .reg .u64 t; cvta.to.shared.u64 t, %1; cvt.u32.u64 %0, t; }"
        : "=r"(a) : "l"(p));
    return a;
}

#define LDSM_X4(d, a) \
    asm volatile("ldmatrix.sync.aligned.m8n8.x4.shared.b16 {%0,%1,%2,%3}, [%4];" \
        : "=r"((d)[0]), "=r"((d)[1]), "=r"((d)[2]), "=r"((d)[3]) : "r"(a))

#define MMA_BF16(c, a, b0, b1) \
    asm volatile("mma.sync.aligned.m16n8k16.row.col.f32.bf16.bf16.f32 " \
        "{%0,%1,%2,%3}, {%4,%5,%6,%7}, {%8,%9}, {%0,%1,%2,%3};" \
        : "+f"((c)[0]), "+f"((c)[1]), "+f"((c)[2]), "+f"((c)[3]) \
        : "r"((a)[0]), "r"((a)[1]), "r"((a)[2]), "r"((a)[3]), "r"(b0), "r"(b1))

#define CP_ASYNC16(dst, src) \
    asm volatile("cp.async.ca.shared.global [%0], [%1], 16;" :: "r"(dst), "l"(src))
#define CP_COMMIT() asm volatile("cp.async.commit_group;")
#define CP_WAIT0()  asm volatile("cp.async.wait_group 0;")

// ---------------- edge-index dtype sniff ----------------
__device__ __forceinline__ bool ei_is_int64(const int* __restrict__ w) {
    bool z = true;
#pragma unroll
    for (int i = 1; i < 32; i += 2) z &= (w[i] == 0);
    return z;
}

__global__ void k_convert_hist(const int* __restrict__ ei_raw, int* __restrict__ ei32,
                               int* __restrict__ deg) {
    int e = blockIdx.x * blockDim.x + threadIdx.x;
    if (e >= N_EDGES) return;
    bool is64 = ei_is_int64(ei_raw);
    int r = is64 ? ei_raw[2 * e] : ei_raw[e];
    int c = is64 ? ei_raw[2 * (N_EDGES + e)] : ei_raw[N_EDGES + e];
    ei32[e] = r;
    ei32[N_EDGES + e] = c;
    atomicAdd(&deg[c], 1);
}

// ---------------- W prep ----------------
__global__ void k_wprep(const float* __restrict__ W) {
    int i = blockIdx.x * blockDim.x + threadIdx.x;
    if (i >= 3 * 128 * 128) return;
    int l = i >> 14;
    int rem = i & 16383;
    int k = rem >> 7;
    int n = rem & 127;
    float w = W[l * 16384 + k * 128 + n];
    __nv_bfloat16 hb = __float2bfloat16_rn(w);
    float hf = __bfloat162float(hb);
    __nv_bfloat16 lb = __float2bfloat16_rn(w - hf);
    uint32_t pos = swz(n, k * 2);
    *(__nv_bfloat16*)(g_wt + (size_t)(l * 2 + 0) * 32768 + pos) = hb;
    *(__nv_bfloat16*)(g_wt + (size_t)(l * 2 + 1) * 32768 + pos) = lb;
}

// ---------------- prep ----------------
__global__ void k_zeroi(int* __restrict__ p, int n) {
    int i = blockIdx.x * blockDim.x + threadIdx.x;
    if (i < n) p[i] = 0;
}

__global__ __launch_bounds__(256) void k_dinv_bsum(const int* __restrict__ deg,
                                                   float* __restrict__ dinv,
                                                   int* __restrict__ bsum) {
    __shared__ int s[256];
    int b = blockIdx.x, t = threadIdx.x;
    int base = b * SCAN_BS + t * 4;
    int v = 0;
#pragma unroll
    for (int j = 0; j < 4; j++) {
        int i = base + j;
        if (i < N_NODES) {
            int d = deg[i];
            dinv[i] = (d > 0) ? rsqrtf((float)d) : 0.f;
            v += d;
        }
    }
    s[t] = v;
    __syncthreads();
    for (int off = 128; off > 0; off >>= 1) {
        if (t < off) s[t] += s[t + off];
        __syncthreads();
    }
    if (t == 0) bsum[b] = s[0];
}

__global__ __launch_bounds__(128) void k_scansums(const int* __restrict__ bsum,
                                                  int* __restrict__ boff,
                                                  int* __restrict__ rowptr) {
    __shared__ int s[128];
    int t = threadIdx.x;
    int v = (t < N_SCAN_BLOCKS) ? bsum[t] : 0;
    s[t] = v;
    __syncthreads();
    for (int off = 1; off < 128; off <<= 1) {
        int u = (t >= off) ? s[t - off] : 0;
        __syncthreads();
        s[t] += u;
        __syncthreads();
    }
    if (t < N_SCAN_BLOCKS) boff[t] = s[t] - v;
    if (t == N_SCAN_BLOCKS - 1) rowptr[N_NODES] = s[t];
}

__global__ __launch_bounds__(SCAN_BS) void k_scanapply(const int* __restrict__ deg,
                                                       const int* __restrict__ boff,
                                                       int* __restrict__ rowptr,
                                                       int* __restrict__ cursor) {
    __shared__ int s[SCAN_BS];
    int b = blockIdx.x, t = threadIdx.x;
    int i = b * SCAN_BS + t;
    int v = (i < N_NODES) ? deg[i] : 0;
    s[t] = v;
    __syncthreads();
    for (int off = 1; off < SCAN_BS; off <<= 1) {
        int u = (t >= off) ? s[t - off] : 0;
        __syncthreads();
        s[t] += u;
        __syncthreads();
    }
    if (i < N_NODES) {
        int excl = boff[b] + s[t] - v;
        rowptr[i] = excl;
        cursor[i] = excl;
    }
}

__global__ void k_fill(const int* __restrict__ ei, const float* __restrict__ dinv,
                       int* __restrict__ cursor, int* __restrict__ esrc,
                       float* __restrict__ enorm) {
    int e = blockIdx.x * blockDim.x + threadIdx.x;
    if (e >= N_EDGES) return;
    int r = ei[e];
    int c = ei[N_EDGES + e];
    int pos = atomicAdd(&cursor[c], 1);
    esrc[pos] = r;
    enorm[pos] = dinv[r] * dinv[c];
}

// ---------------- GEMM common ----------------
#define OFF_AH 0u
#define OFF_AL 16384u
#define OFF_WH 32768u
#define OFF_WL 65536u
#define GEMM_SMEM 98304
#define GEMM_TPB 256

__device__ __forceinline__ uint2 pack4(float x, float y, float z, float w) {
    __nv_bfloat162 p0 = __floats2bfloat162_rn(x, y);
    __nv_bfloat162 p1 = __floats2bfloat162_rn(z, w);
    return make_uint2(*(uint32_t*)&p0, *(uint32_t*)&p1);
}

__device__ __forceinline__ void split_pair(float4 v, uint2& hi, uint2& lo) {
    hi = pack4(v.x, v.y, v.z, v.w);
    float hx = __bfloat162float(__float2bfloat16_rn(v.x));
    float hy = __bfloat162float(__float2bfloat16_rn(v.y));
    float hz = __bfloat162float(__float2bfloat16_rn(v.z));
    float hw = __bfloat162float(__float2bfloat16_rn(v.w));
    lo = pack4(v.x - hx, v.y - hy, v.z - hz, v.w - hw);
}

__device__ __forceinline__ void w_copy_async(uint32_t sb, int tid, int layer) {
    const unsigned char* sh = g_wt + (size_t)(layer * 2 + 0) * 32768;
    const unsigned char* sl = g_wt + (size_t)(layer * 2 + 1) * 32768;
#pragma unroll
    for (int j = 0; j < 8; j++) {
        uint32_t off = (uint32_t)(tid + j * 256) * 16;
        CP_ASYNC16(sb + OFF_WH + off, sh + off);
        CP_ASYNC16(sb + OFF_WL + off, sl + off);
    }
}

__device__ __forceinline__ void mma_main_epi(uint32_t sb, int tid, int row0,
                                             float* __restrict__ H) {
    const int w = tid >> 5;
    const int lane = tid & 31;
    const int wm = w >> 2;
    const int wn = w & 3;

    float acc[2][4][4];
#pragma unroll
    for (int mi = 0; mi < 2; mi++)
#pragma unroll
        for (int ni = 0; ni < 4; ni++)
#pragma unroll
            for (int j = 0; j < 4; j++) acc[mi][ni][j] = 0.f;

    const int a_row = wm * 32 + (lane & 15);
    const int a_kb  = (lane >> 4) << 4;
    const int b_row = wn * 32 + ((lane >> 4) << 3) + (lane & 7);
    const int b_kb  = ((lane >> 3) & 1) << 4;

#pragma unroll
    for (int ks = 0; ks < 8; ks++) {
        uint32_t ah[2][4], al[2][4], bh[2][4], bl[2][4];
#pragma unroll
        for (int mi = 0; mi < 2; mi++) {
            uint32_t addr = swz(a_row + mi * 16, a_kb + ks * 32);
            LDSM_X4(ah[mi], sb + OFF_AH + addr);
            LDSM_X4(al[mi], sb + OFF_AL + addr);
        }
#pragma unroll
        for (int p = 0; p < 2; p++) {
            uint32_t addr = swz(b_row + p * 16, b_kb + ks * 32);
            LDSM_X4(bh[p], sb + OFF_WH + addr);
            LDSM_X4(bl[p], sb + OFF_WL + addr);
        }
#pragma unroll
        for (int mi = 0; mi < 2; mi++) {
#pragma unroll
            for (int p = 0; p < 2; p++) {
#pragma unroll
                for (int s = 0; s < 2; s++) {
                    int ni = p * 2 + s;
                    MMA_BF16(acc[mi][ni], ah[mi], bh[p][s * 2], bh[p][s * 2 + 1]);
                    MMA_BF16(acc[mi][ni], ah[mi], bl[p][s * 2], bl[p][s * 2 + 1]);
                    MMA_BF16(acc[mi][ni], al[mi], bh[p][s * 2], bh[p][s * 2 + 1]);
                }
            }
        }
    }

#pragma unroll
    for (int mi = 0; mi < 2; mi++) {
        int r1 = row0 + wm * 32 + mi * 16 + (lane >> 2);
        int r2 = r1 + 8;
#pragma unroll
        for (int ni = 0; ni < 4; ni++) {
            int col = wn * 32 + ni * 8 + 2 * (lane & 3);
            if (r1 < N_NODES)
                *(float2*)(H + (size_t)r1 * D + col) = make_float2(acc[mi][ni][0], acc[mi][ni][1]);
            if (r2 < N_NODES)
                *(float2*)(H + (size_t)r2 * D + col) = make_float2(acc[mi][ni][2], acc[mi][ni][3]);
        }
    }
}

// ---------------- dense GEMM (layer 0): H = X @ W0 ----------------
__global__ __launch_bounds__(GEMM_TPB, 2) void k_gemm0(const float* __restrict__ X,
                                                       float* __restrict__ H) {
    extern __shared__ unsigned char smem[];
    const uint32_t sb = s2u(smem);
    const int tid = threadIdx.x;
    const int row0 = blockIdx.x * M_TILE;

    w_copy_async(sb, tid, 0);
    CP_COMMIT();

    {
        int r = tid >> 2;
        int q = tid & 3;
        int gr = row0 + r;
        bool valid = gr < N_NODES;
        const float4* src = (const float4*)(X + (size_t)gr * D);
#pragma unroll
        for (int j = 0; j < 8; j++) {
            int qp = q + j * 4;
            float4 v = valid ? src[qp] : make_float4(0.f, 0.f, 0.f, 0.f);
            uint2 hi, lo;
            split_pair(v, hi, lo);
            uint32_t addr = swz(r, qp * 8);
            *(uint2*)(smem + OFF_AH + addr) = hi;
            *(uint2*)(smem + OFF_AL + addr) = lo;
        }
    }
    CP_WAIT0();
    __syncthreads();
    mma_main_epi(sb, tid, row0, H);
}

// ---------------- pre-split GEMM (layers 1,2): pure cp.async staging ----------------
__global__ __launch_bounds__(GEMM_TPB, 2) void k_gemm_ps(int layer,
                                                         float* __restrict__ H) {
    extern __shared__ unsigned char smem[];
    const uint32_t sb = s2u(smem);
    const int tid = threadIdx.x;
    const int row0 = blockIdx.x * M_TILE;

    w_copy_async(sb, tid, layer);
    {
        const unsigned char* ah = g_ahi + (size_t)blockIdx.x * 16384;
        const unsigned char* al = g_alo + (size_t)blockIdx.x * 16384;
#pragma unroll
        for (int j = 0; j < 4; j++) {
            uint32_t off = (uint32_t)(tid + j * 256) * 16;
            CP_ASYNC16(sb + OFF_AH + off, ah + off);
            CP_ASYNC16(sb + OFF_AL + off, al + off);
        }
    }
    CP_COMMIT();
    CP_WAIT0();
    __syncthreads();
    mma_main_epi(sb, tid, row0, H);
}

// ---------------- CSR gather ----------------
// SPLIT=true: fused bias+relu+bf16-split, writes swizzled tile images.
// SPLIT=false: bias only, writes fp32 rows to out.
template <bool SPLIT>
__global__ __launch_bounds__(256) void k_gather(const int* __restrict__ rowptr,
                                                const int* __restrict__ esrc,
                                                const float* __restrict__ enorm,
                                                const float* __restrict__ H,
                                                const float* __restrict__ bvec,
                                                float* __restrict__ out) {
    int n = blockIdx.x * 8 + (threadIdx.x >> 5);
    if (n >= N_NODES) return;
    int lane = threadIdx.x & 31;

    float4 acc = ((const float4*)bvec)[lane];

    int e = rowptr[n];
    int end = rowptr[n + 1];
    for (; e + 4 <= end; e += 4) {
        int s0 = esrc[e], s1 = esrc[e + 1], s2 = esrc[e + 2], s3 = esrc[e + 3];
        float n0 = enorm[e], n1 = enorm[e + 1], n2 = enorm[e + 2], n3 = enorm[e + 3];
        float4 v0 = __ldg(&((const float4*)(H + (size_t)s0 * D))[lane]);
        float4 v1 = __ldg(&((const float4*)(H + (size_t)s1 * D))[lane]);
        float4 v2 = __ldg(&((const float4*)(H + (size_t)s2 * D))[lane]);
        float4 v3 = __ldg(&((const float4*)(H + (size_t)s3 * D))[lane]);
        acc.x += v0.x * n0 + v1.x * n1 + v2.x * n2 + v3.x * n3;
        acc.y += v0.y * n0 + v1.y * n1 + v2.y * n2 + v3.y * n3;
        acc.z += v0.z * n0 + v1.z * n1 + v2.z * n2 + v3.z * n3;
        acc.w += v0.w * n0 + v1.w * n1 + v2.w * n2 + v3.w * n3;
    }
    for (; e < end; e++) {
        int s0 = esrc[e];
        float n0 = enorm[e];
        float4 v0 = __ldg(&((const float4*)(H + (size_t)s0 * D))[lane]);
        acc.x += v0.x * n0; acc.y += v0.y * n0;
        acc.z += v0.z * n0; acc.w += v0.w * n0;
    }

    if (SPLIT) {
        acc.x = fmaxf(acc.x, 0.f); acc.y = fmaxf(acc.y, 0.f);
        acc.z = fmaxf(acc.z, 0.f); acc.w = fmaxf(acc.w, 0.f);
        uint2 hi, lo;
        split_pair(acc, hi, lo);
        size_t base = (size_t)(n >> 6) * 16384 + swz(n & 63, lane * 8);
        *(uint2*)(g_ahi + base) = hi;
        *(uint2*)(g_alo + base) = lo;
    } else {
        ((float4*)(out + (size_t)n * D))[lane] = acc;
    }
}

// ---------------- launch (R6 schedule) ----------------
extern "C" void kernel_launch(void* const* d_in, const int* in_sizes, int n_in,
                              void* d_out, int out_size) {
    const float* x = (const float*)d_in[0];
    const int* ei_raw = (const int*)d_in[1];
    const float* W = (const float*)d_in[3];
    const float* b = (const float*)d_in[4];
    float* out = (float*)d_out;

    float *dinv, *h, *h2, *enorm;
    int *deg, *rowptr, *cursor, *bsum, *boff, *esrc, *ei;
    cudaGetSymbolAddress((void**)&dinv, g_dinv);
    cudaGetSymbolAddress((void**)&h, g_h);
    cudaGetSymbolAddress((void**)&h2, g_h2);
    cudaGetSymbolAddress((void**)&enorm, g_enorm);
    cudaGetSymbolAddress((void**)&deg, g_deg);
    cudaGetSymbolAddress((void**)&rowptr, g_rowptr);
    cudaGetSymbolAddress((void**)&cursor, g_cursor);
    cudaGetSymbolAddress((void**)&bsum, g_bsum);
    cudaGetSymbolAddress((void**)&boff, g_boff);
    cudaGetSymbolAddress((void**)&esrc, g_esrc);
    cudaGetSymbolAddress((void**)&ei, g_ei);

    cudaFuncSetAttribute(k_gemm0, cudaFuncAttributeMaxDynamicSharedMemorySize, GEMM_SMEM);
    cudaFuncSetAttribute(k_gemm_ps, cudaFuncAttributeMaxDynamicSharedMemorySize, GEMM_SMEM);

    const int TPB = 256;
    const int GATH_BLOCKS = (N_NODES + 7) / 8;

    // fork: gemm0 (+wprep) overlaps the edge-prep chain
    cudaStream_t s2;
    cudaEvent_t evFork, evJoin;
    cudaStreamCreateWithFlags(&s2, cudaStreamNonBlocking);
    cudaEventCreateWithFlags(&evFork, cudaEventDisableTiming);
    cudaEventCreateWithFlags(&evJoin, cudaEventDisableTiming);

    cudaEventRecord(evFork, 0);
    cudaStreamWaitEvent(s2, evFork, 0);

    k_wprep<<<(3 * 128 * 128 + TPB - 1) / TPB, TPB, 0, s2>>>(W);
    k_gemm0<<<GEMM_BLOCKS, GEMM_TPB, GEMM_SMEM, s2>>>(x, h);
    cudaEventRecord(evJoin, s2);

    k_zeroi<<<(N_NODES + TPB - 1) / TPB, TPB>>>(deg, N_NODES);
    k_convert_hist<<<(N_EDGES + TPB - 1) / TPB, TPB>>>(ei_raw, ei, deg);
    k_dinv_bsum<<<N_SCAN_BLOCKS, 256>>>(deg, dinv, bsum);
    k_scansums<<<1, 128>>>(bsum, boff, rowptr);
    k_scanapply<<<N_SCAN_BLOCKS, SCAN_BS>>>(deg, boff, rowptr, cursor);
    k_fill<<<(N_EDGES + TPB - 1) / TPB, TPB>>>(ei, dinv, cursor, esrc, enorm);

    cudaStreamWaitEvent(0, evJoin, 0);

    // layer 1: gather(h)+b0+relu -> split images; GEMM W1 -> h2
    k_gather<true><<<GATH_BLOCKS, TPB>>>(rowptr, esrc, enorm, h, b + 0 * D, nullptr);
    k_gemm_ps<<<GEMM_BLOCKS, GEMM_TPB, GEMM_SMEM>>>(1, h2);
    // layer 2: gather(h2)+b1+relu -> split images; GEMM W2 -> h
    k_gather<true><<<GATH_BLOCKS, TPB>>>(rowptr, esrc, enorm, h2, b + 1 * D, nullptr);
    k_gemm_ps<<<GEMM_BLOCKS, GEMM_TPB, GEMM_SMEM>>>(2, h);
    // final: gather(h)+b2 -> out
    k_gather<false><<<GATH_BLOCKS, TPB>>>(rowptr, esrc, enorm, h, b + 2 * D, out);
}

// round 11
// speedup vs baseline: 1.3010x; 1.0509x over previous
#include <cuda_runtime.h>
#include <cuda_bf16.h>
#include <cuda_fp16.h>
#include <cstdint>

#define N_NODES 100000
#define N_EDGES 640000
#define D 128
#define SCAN_BS 1024
#define N_SCAN_BLOCKS ((N_NODES + SCAN_BS - 1) / SCAN_BS)  // 98
#define M_TILE 64
#define GEMM_BLOCKS ((N_NODES + M_TILE - 1) / M_TILE)      // 1563

// ---- scratch ----
__device__ __half g_h[(size_t)N_NODES * D];
__device__ __half g_h2[(size_t)N_NODES * D];
// pre-split, pre-swizzled A-tile images (bf16): [tile][64 rows][256B]
__device__ unsigned char g_ahi[(size_t)GEMM_BLOCKS * 16384];
__device__ unsigned char g_alo[(size_t)GEMM_BLOCKS * 16384];
__device__ int   g_deg[N_NODES];
__device__ float g_dinv[N_NODES];
__device__ int   g_rowptr[N_NODES + 1];
__device__ int   g_cursor[N_NODES];
__device__ int   g_bsum[128];
__device__ int   g_boff[128];
__device__ int   g_esrc[N_EDGES];
__device__ float g_enorm[N_EDGES];
__device__ int   g_ei[2 * N_EDGES];
__device__ unsigned char g_wt[3 * 2 * 32768];

__device__ __forceinline__ uint32_t swz(int row, int kb) {
    return (uint32_t)(row * 256 + (kb ^ ((row & 7) << 4)));
}

__device__ __forceinline__ uint32_t s2u(const void* p) {
    uint32_t a;
    asm("{ .reg .u64 t; cvta.to.shared.u64 t, %1; cvt.u32.u64 %0, t; }"
        : "=r"(a) : "l"(p));
    return a;
}

#define LDSM_X4(d, a) \
    asm volatile("ldmatrix.sync.aligned.m8n8.x4.shared.b16 {%0,%1,%2,%3}, [%4];" \
        : "=r"((d)[0]), "=r"((d)[1]), "=r"((d)[2]), "=r"((d)[3]) : "r"(a))

#define MMA_BF16(c, a, b0, b1) \
    asm volatile("mma.sync.aligned.m16n8k16.row.col.f32.bf16.bf16.f32 " \
        "{%0,%1,%2,%3}, {%4,%5,%6,%7}, {%8,%9}, {%0,%1,%2,%3};" \
        : "+f"((c)[0]), "+f"((c)[1]), "+f"((c)[2]), "+f"((c)[3]) \
        : "r"((a)[0]), "r"((a)[1]), "r"((a)[2]), "r"((a)[3]), "r"(b0), "r"(b1))

#define CP_ASYNC16(dst, src) \
    asm volatile("cp.async.ca.shared.global [%0], [%1], 16;" :: "r"(dst), "l"(src))
#define CP_COMMIT() asm volatile("cp.async.commit_group;")
#define CP_WAIT0()  asm volatile("cp.async.wait_group 0;")

// ---------------- edge-index dtype sniff ----------------
__device__ __forceinline__ bool ei_is_int64(const int* __restrict__ w) {
    bool z = true;
#pragma unroll
    for (int i = 1; i < 32; i += 2) z &= (w[i] == 0);
    return z;
}

__global__ void k_convert_hist(const int* __restrict__ ei_raw, int* __restrict__ ei32,
                               int* __restrict__ deg) {
    int e = blockIdx.x * blockDim.x + threadIdx.x;
    if (e >= N_EDGES) return;
    bool is64 = ei_is_int64(ei_raw);
    int r = is64 ? ei_raw[2 * e] : ei_raw[e];
    int c = is64 ? ei_raw[2 * (N_EDGES + e)] : ei_raw[N_EDGES + e];
    ei32[e] = r;
    ei32[N_EDGES + e] = c;
    atomicAdd(&deg[c], 1);
}

// ---------------- W prep ----------------
__global__ void k_wprep(const float* __restrict__ W) {
    int i = blockIdx.x * blockDim.x + threadIdx.x;
    if (i >= 3 * 128 * 128) return;
    int l = i >> 14;
    int rem = i & 16383;
    int k = rem >> 7;
    int n = rem & 127;
    float w = W[l * 16384 + k * 128 + n];
    __nv_bfloat16 hb = __float2bfloat16_rn(w);
    float hf = __bfloat162float(hb);
    __nv_bfloat16 lb = __float2bfloat16_rn(w - hf);
    uint32_t pos = swz(n, k * 2);
    *(__nv_bfloat16*)(g_wt + (size_t)(l * 2 + 0) * 32768 + pos) = hb;
    *(__nv_bfloat16*)(g_wt + (size_t)(l * 2 + 1) * 32768 + pos) = lb;
}

// ---------------- prep ----------------
__global__ void k_zeroi(int* __restrict__ p, int n) {
    int i = blockIdx.x * blockDim.x + threadIdx.x;
    if (i < n) p[i] = 0;
}

__global__ __launch_bounds__(256) void k_dinv_bsum(const int* __restrict__ deg,
                                                   float* __restrict__ dinv,
                                                   int* __restrict__ bsum) {
    __shared__ int s[256];
    int b = blockIdx.x, t = threadIdx.x;
    int base = b * SCAN_BS + t * 4;
    int v = 0;
#pragma unroll
    for (int j = 0; j < 4; j++) {
        int i = base + j;
        if (i < N_NODES) {
            int d = deg[i];
            dinv[i] = (d > 0) ? rsqrtf((float)d) : 0.f;
            v += d;
        }
    }
    s[t] = v;
    __syncthreads();
    for (int off = 128; off > 0; off >>= 1) {
        if (t < off) s[t] += s[t + off];
        __syncthreads();
    }
    if (t == 0) bsum[b] = s[0];
}

__global__ __launch_bounds__(128) void k_scansums(const int* __restrict__ bsum,
                                                  int* __restrict__ boff,
                                                  int* __restrict__ rowptr) {
    __shared__ int s[128];
    int t = threadIdx.x;
    int v = (t < N_SCAN_BLOCKS) ? bsum[t] : 0;
    s[t] = v;
    __syncthreads();
    for (int off = 1; off < 128; off <<= 1) {
        int u = (t >= off) ? s[t - off] : 0;
        __syncthreads();
        s[t] += u;
        __syncthreads();
    }
    if (t < N_SCAN_BLOCKS) boff[t] = s[t] - v;
    if (t == N_SCAN_BLOCKS - 1) rowptr[N_NODES] = s[t];
}

__global__ __launch_bounds__(SCAN_BS) void k_scanapply(const int* __restrict__ deg,
                                                       const int* __restrict__ boff,
                                                       int* __restrict__ rowptr,
                                                       int* __restrict__ cursor) {
    __shared__ int s[SCAN_BS];
    int b = blockIdx.x, t = threadIdx.x;
    int i = b * SCAN_BS + t;
    int v = (i < N_NODES) ? deg[i] : 0;
    s[t] = v;
    __syncthreads();
    for (int off = 1; off < SCAN_BS; off <<= 1) {
        int u = (t >= off) ? s[t - off] : 0;
        __syncthreads();
        s[t] += u;
        __syncthreads();
    }
    if (i < N_NODES) {
        int excl = boff[b] + s[t] - v;
        rowptr[i] = excl;
        cursor[i] = excl;
    }
}

__global__ void k_fill(const int* __restrict__ ei, const float* __restrict__ dinv,
                       int* __restrict__ cursor, int* __restrict__ esrc,
                       float* __restrict__ enorm) {
    int e = blockIdx.x * blockDim.x + threadIdx.x;
    if (e >= N_EDGES) return;
    int r = ei[e];
    int c = ei[N_EDGES + e];
    int pos = atomicAdd(&cursor[c], 1);
    esrc[pos] = r;
    enorm[pos] = dinv[r] * dinv[c];
}

// ---------------- GEMM common ----------------
#define OFF_AH 0u
#define OFF_AL 16384u
#define OFF_WH 32768u
#define OFF_WL 65536u
#define GEMM_SMEM 98304
#define GEMM_TPB 256

__device__ __forceinline__ uint2 pack4(float x, float y, float z, float w) {
    __nv_bfloat162 p0 = __floats2bfloat162_rn(x, y);
    __nv_bfloat162 p1 = __floats2bfloat162_rn(z, w);
    return make_uint2(*(uint32_t*)&p0, *(uint32_t*)&p1);
}

__device__ __forceinline__ void split_pair(float4 v, uint2& hi, uint2& lo) {
    hi = pack4(v.x, v.y, v.z, v.w);
    float hx = __bfloat162float(__float2bfloat16_rn(v.x));
    float hy = __bfloat162float(__float2bfloat16_rn(v.y));
    float hz = __bfloat162float(__float2bfloat16_rn(v.z));
    float hw = __bfloat162float(__float2bfloat16_rn(v.w));
    lo = pack4(v.x - hx, v.y - hy, v.z - hz, v.w - hw);
}

__device__ __forceinline__ void w_copy_async(uint32_t sb, int tid, int layer) {
    const unsigned char* sh = g_wt + (size_t)(layer * 2 + 0) * 32768;
    const unsigned char* sl = g_wt + (size_t)(layer * 2 + 1) * 32768;
#pragma unroll
    for (int j = 0; j < 8; j++) {
        uint32_t off = (uint32_t)(tid + j * 256) * 16;
        CP_ASYNC16(sb + OFF_WH + off, sh + off);
        CP_ASYNC16(sb + OFF_WL + off, sl + off);
    }
}

// ---------------- X pre-split (layer 0 staging, runs on side stream) ----------------
__global__ void k_xsplit(const float* __restrict__ X) {
    int idx = blockIdx.x * blockDim.x + threadIdx.x;  // float4 index
    if (idx >= N_NODES * 32) return;
    int n = idx >> 5;
    int qp = idx & 31;
    float4 v = ((const float4*)X)[idx];
    uint2 hi, lo;
    split_pair(v, hi, lo);
    size_t base = (size_t)(n >> 6) * 16384 + swz(n & 63, qp * 8);
    *(uint2*)(g_ahi + base) = hi;
    *(uint2*)(g_alo + base) = lo;
}

// ---------------- pre-split GEMM: H(fp16) = tiles(g_ahi/g_alo) @ W_layer ----------------
__global__ __launch_bounds__(GEMM_TPB, 2) void k_gemm_ps(int layer,
                                                         __half* __restrict__ H) {
    extern __shared__ unsigned char smem[];
    const uint32_t sb = s2u(smem);
    const int tid = threadIdx.x;
    const int w = tid >> 5;
    const int lane = tid & 31;
    const int wm = w >> 2;
    const int wn = w & 3;
    const int row0 = blockIdx.x * M_TILE;

    w_copy_async(sb, tid, layer);
    {
        const unsigned char* ah = g_ahi + (size_t)blockIdx.x * 16384;
        const unsigned char* al = g_alo + (size_t)blockIdx.x * 16384;
#pragma unroll
        for (int j = 0; j < 4; j++) {
            uint32_t off = (uint32_t)(tid + j * 256) * 16;
            CP_ASYNC16(sb + OFF_AH + off, ah + off);
            CP_ASYNC16(sb + OFF_AL + off, al + off);
        }
    }
    CP_COMMIT();
    CP_WAIT0();
    __syncthreads();

    float acc[2][4][4];
#pragma unroll
    for (int mi = 0; mi < 2; mi++)
#pragma unroll
        for (int ni = 0; ni < 4; ni++)
#pragma unroll
            for (int j = 0; j < 4; j++) acc[mi][ni][j] = 0.f;

    const int a_row = wm * 32 + (lane & 15);
    const int a_kb  = (lane >> 4) << 4;
    const int b_row = wn * 32 + ((lane >> 4) << 3) + (lane & 7);
    const int b_kb  = ((lane >> 3) & 1) << 4;

#pragma unroll
    for (int ks = 0; ks < 8; ks++) {
        uint32_t ah[2][4], al[2][4], bh[2][4], bl[2][4];
#pragma unroll
        for (int mi = 0; mi < 2; mi++) {
            uint32_t addr = swz(a_row + mi * 16, a_kb + ks * 32);
            LDSM_X4(ah[mi], sb + OFF_AH + addr);
            LDSM_X4(al[mi], sb + OFF_AL + addr);
        }
#pragma unroll
        for (int p = 0; p < 2; p++) {
            uint32_t addr = swz(b_row + p * 16, b_kb + ks * 32);
            LDSM_X4(bh[p], sb + OFF_WH + addr);
            LDSM_X4(bl[p], sb + OFF_WL + addr);
        }
#pragma unroll
        for (int mi = 0; mi < 2; mi++) {
#pragma unroll
            for (int p = 0; p < 2; p++) {
#pragma unroll
                for (int s = 0; s < 2; s++) {
                    int ni = p * 2 + s;
                    MMA_BF16(acc[mi][ni], ah[mi], bh[p][s * 2], bh[p][s * 2 + 1]);
                    MMA_BF16(acc[mi][ni], ah[mi], bl[p][s * 2], bl[p][s * 2 + 1]);
                    MMA_BF16(acc[mi][ni], al[mi], bh[p][s * 2], bh[p][s * 2 + 1]);
                }
            }
        }
    }

    // epilogue: fp16 stores (halves H traffic for the gathers)
#pragma unroll
    for (int mi = 0; mi < 2; mi++) {
        int r1 = row0 + wm * 32 + mi * 16 + (lane >> 2);
        int r2 = r1 + 8;
#pragma unroll
        for (int ni = 0; ni < 4; ni++) {
            int col = wn * 32 + ni * 8 + 2 * (lane & 3);
            if (r1 < N_NODES)
                *(__half2*)(H + (size_t)r1 * D + col) =
                    __floats2half2_rn(acc[mi][ni][0], acc[mi][ni][1]);
            if (r2 < N_NODES)
                *(__half2*)(H + (size_t)r2 * D + col) =
                    __floats2half2_rn(acc[mi][ni][2], acc[mi][ni][3]);
        }
    }
}

// ---------------- CSR gather over fp16 H ----------------
// SPLIT=true: fused bias+relu+bf16-split, writes swizzled tile images.
// SPLIT=false: bias only, writes fp32 rows to out.
__device__ __forceinline__ void acc_edge(float4& acc, const __half* __restrict__ H,
                                         int s, float nv, int lane) {
    uint2 raw = __ldg((const uint2*)(H + (size_t)s * D) + lane);
    float2 f0 = __half22float2(*(__half2*)&raw.x);
    float2 f1 = __half22float2(*(__half2*)&raw.y);
    acc.x += f0.x * nv; acc.y += f0.y * nv;
    acc.z += f1.x * nv; acc.w += f1.y * nv;
}

template <bool SPLIT>
__global__ __launch_bounds__(256) void k_gather(const int* __restrict__ rowptr,
                                                const int* __restrict__ esrc,
                                                const float* __restrict__ enorm,
                                                const __half* __restrict__ H,
                                                const float* __restrict__ bvec,
                                                float* __restrict__ out) {
    int n = blockIdx.x * 8 + (threadIdx.x >> 5);
    if (n >= N_NODES) return;
    int lane = threadIdx.x & 31;

    float4 acc = ((const float4*)bvec)[lane];

    int e = rowptr[n];
    int end = rowptr[n + 1];
    for (; e + 4 <= end; e += 4) {
        int s0 = esrc[e], s1 = esrc[e + 1], s2 = esrc[e + 2], s3 = esrc[e + 3];
        float n0 = enorm[e], n1 = enorm[e + 1], n2 = enorm[e + 2], n3 = enorm[e + 3];
        acc_edge(acc, H, s0, n0, lane);
        acc_edge(acc, H, s1, n1, lane);
        acc_edge(acc, H, s2, n2, lane);
        acc_edge(acc, H, s3, n3, lane);
    }
    for (; e < end; e++) {
        acc_edge(acc, H, esrc[e], enorm[e], lane);
    }

    if (SPLIT) {
        acc.x = fmaxf(acc.x, 0.f); acc.y = fmaxf(acc.y, 0.f);
        acc.z = fmaxf(acc.z, 0.f); acc.w = fmaxf(acc.w, 0.f);
        uint2 hi, lo;
        split_pair(acc, hi, lo);
        size_t base = (size_t)(n >> 6) * 16384 + swz(n & 63, lane * 8);
        *(uint2*)(g_ahi + base) = hi;
        *(uint2*)(g_alo + base) = lo;
    } else {
        ((float4*)(out + (size_t)n * D))[lane] = acc;
    }
}

// ---------------- launch ----------------
extern "C" void kernel_launch(void* const* d_in, const int* in_sizes, int n_in,
                              void* d_out, int out_size) {
    const float* x = (const float*)d_in[0];
    const int* ei_raw = (const int*)d_in[1];
    const float* W = (const float*)d_in[3];
    const float* b = (const float*)d_in[4];
    float* out = (float*)d_out;

    float *dinv, *enorm;
    __half *h, *h2;
    int *deg, *rowptr, *cursor, *bsum, *boff, *esrc, *ei;
    cudaGetSymbolAddress((void**)&dinv, g_dinv);
    cudaGetSymbolAddress((void**)&h, g_h);
    cudaGetSymbolAddress((void**)&h2, g_h2);
    cudaGetSymbolAddress((void**)&enorm, g_enorm);
    cudaGetSymbolAddress((void**)&deg, g_deg);
    cudaGetSymbolAddress((void**)&rowptr, g_rowptr);
    cudaGetSymbolAddress((void**)&cursor, g_cursor);
    cudaGetSymbolAddress((void**)&bsum, g_bsum);
    cudaGetSymbolAddress((void**)&boff, g_boff);
    cudaGetSymbolAddress((void**)&esrc, g_esrc);
    cudaGetSymbolAddress((void**)&ei, g_ei);

    cudaFuncSetAttribute(k_gemm_ps, cudaFuncAttributeMaxDynamicSharedMemorySize, GEMM_SMEM);

    const int TPB = 256;
    const int GATH_BLOCKS = (N_NODES + 7) / 8;

    // fork: wprep + xsplit + gemm0 overlap the edge-prep chain
    cudaStream_t s2;
    cudaEvent_t evFork, evJoin;
    cudaStreamCreateWithFlags(&s2, cudaStreamNonBlocking);
    cudaEventCreateWithFlags(&evFork, cudaEventDisableTiming);
    cudaEventCreateWithFlags(&evJoin, cudaEventDisableTiming);

    cudaEventRecord(evFork, 0);
    cudaStreamWaitEvent(s2, evFork, 0);

    k_wprep<<<(3 * 128 * 128 + TPB - 1) / TPB, TPB, 0, s2>>>(W);
    k_xsplit<<<(N_NODES * 32 + TPB - 1) / TPB, TPB, 0, s2>>>(x);
    k_gemm_ps<<<GEMM_BLOCKS, GEMM_TPB, GEMM_SMEM, s2>>>(0, h);
    cudaEventRecord(evJoin, s2);

    k_zeroi<<<(N_NODES + TPB - 1) / TPB, TPB>>>(deg, N_NODES);
    k_convert_hist<<<(N_EDGES + TPB - 1) / TPB, TPB>>>(ei_raw, ei, deg);
    k_dinv_bsum<<<N_SCAN_BLOCKS, 256>>>(deg, dinv, bsum);
    k_scansums<<<1, 128>>>(bsum, boff, rowptr);
    k_scanapply<<<N_SCAN_BLOCKS, SCAN_BS>>>(deg, boff, rowptr, cursor);
    k_fill<<<(N_EDGES + TPB - 1) / TPB, TPB>>>(ei, dinv, cursor, esrc, enorm);

    cudaStreamWaitEvent(0, evJoin, 0);

    // layer 1: gather(h)+b0+relu -> split images; GEMM W1 -> h2
    k_gather<true><<<GATH_BLOCKS, TPB>>>(rowptr, esrc, enorm, h, b + 0 * D, nullptr);
    k_gemm_ps<<<GEMM_BLOCKS, GEMM_TPB, GEMM_SMEM>>>(1, h2);
    // layer 2: gather(h2)+b1+relu -> split images; GEMM W2 -> h
    k_gather<true><<<GATH_BLOCKS, TPB>>>(rowptr, esrc, enorm, h2, b + 1 * D, nullptr);
    k_gemm_ps<<<GEMM_BLOCKS, GEMM_TPB, GEMM_SMEM>>>(2, h);
    // final: gather(h)+b2 -> out (fp32)
    k_gather<false><<<GATH_BLOCKS, TPB>>>(rowptr, esrc, enorm, h, b + 2 * D, out);
}

// round 12
// speedup vs baseline: 1.4742x; 1.1331x over previous
#include <cuda_runtime.h>
#include <cuda_fp16.h>
#include <cstdint>

#define N_NODES 100000
#define N_EDGES 640000
#define D 128
#define SCAN_BS 1024
#define N_SCAN_BLOCKS ((N_NODES + SCAN_BS - 1) / SCAN_BS)  // 98
#define M_TILE 64
#define GEMM_BLOCKS ((N_NODES + M_TILE - 1) / M_TILE)      // 1563

// ---- scratch ----
__device__ __half g_h[(size_t)N_NODES * D];
__device__ __half g_h2[(size_t)N_NODES * D];
// pre-swizzled fp16 A-tile images: [tile][64 rows][256B] = 16KB/tile
__device__ unsigned char g_ahi[(size_t)GEMM_BLOCKS * 16384];
__device__ int   g_deg[N_NODES];
__device__ float g_dinv[N_NODES];
__device__ int   g_rowptr[N_NODES + 1];
__device__ int   g_cursor[N_NODES];
__device__ int   g_bsum[128];
__device__ int   g_boff[128];
__device__ int   g_esrc[N_EDGES];
__device__ float g_enorm[N_EDGES];
__device__ int   g_ei[2 * N_EDGES];
// W transposed, fp16 hi/lo split, pre-swizzled: [layer][hi|lo] 32KB each
__device__ unsigned char g_wt[3 * 2 * 32768];

__device__ __forceinline__ uint32_t swz(int row, int kb) {
    return (uint32_t)(row * 256 + (kb ^ ((row & 7) << 4)));
}

__device__ __forceinline__ uint32_t s2u(const void* p) {
    uint32_t a;
    asm("{ .reg .u64 t; cvta.to.shared.u64 t, %1; cvt.u32.u64 %0, t; }"
        : "=r"(a) : "l"(p));
    return a;
}

#define LDSM_X4(d, a) \
    asm volatile("ldmatrix.sync.aligned.m8n8.x4.shared.b16 {%0,%1,%2,%3}, [%4];" \
        : "=r"((d)[0]), "=r"((d)[1]), "=r"((d)[2]), "=r"((d)[3]) : "r"(a))

#define MMA_F16(c, a, b0, b1) \
    asm volatile("mma.sync.aligned.m16n8k16.row.col.f32.f16.f16.f32 " \
        "{%0,%1,%2,%3}, {%4,%5,%6,%7}, {%8,%9}, {%0,%1,%2,%3};" \
        : "+f"((c)[0]), "+f"((c)[1]), "+f"((c)[2]), "+f"((c)[3]) \
        : "r"((a)[0]), "r"((a)[1]), "r"((a)[2]), "r"((a)[3]), "r"(b0), "r"(b1))

#define CP_ASYNC16(dst, src) \
    asm volatile("cp.async.ca.shared.global [%0], [%1], 16;" :: "r"(dst), "l"(src))
#define CP_COMMIT() asm volatile("cp.async.commit_group;")
#define CP_WAIT0()  asm volatile("cp.async.wait_group 0;")

// ---------------- edge-index dtype sniff ----------------
__device__ __forceinline__ bool ei_is_int64(const int* __restrict__ w) {
    bool z = true;
#pragma unroll
    for (int i = 1; i < 32; i += 2) z &= (w[i] == 0);
    return z;
}

__global__ void k_convert_hist(const int* __restrict__ ei_raw, int* __restrict__ ei32,
                               int* __restrict__ deg) {
    int e = blockIdx.x * blockDim.x + threadIdx.x;
    if (e >= N_EDGES) return;
    bool is64 = ei_is_int64(ei_raw);
    int r = is64 ? ei_raw[2 * e] : ei_raw[e];
    int c = is64 ? ei_raw[2 * (N_EDGES + e)] : ei_raw[N_EDGES + e];
    ei32[e] = r;
    ei32[N_EDGES + e] = c;
    atomicAdd(&deg[c], 1);
}

// ---------------- W prep: transpose + fp16 hi/lo split + swizzle ----------------
__global__ void k_wprep(const float* __restrict__ W) {
    int i = blockIdx.x * blockDim.x + threadIdx.x;
    if (i >= 3 * 128 * 128) return;
    int l = i >> 14;
    int rem = i & 16383;
    int k = rem >> 7;
    int n = rem & 127;
    float w = W[l * 16384 + k * 128 + n];
    __half hb = __float2half_rn(w);
    __half lb = __float2half_rn(w - __half2float(hb));
    uint32_t pos = swz(n, k * 2);
    *(__half*)(g_wt + (size_t)(l * 2 + 0) * 32768 + pos) = hb;
    *(__half*)(g_wt + (size_t)(l * 2 + 1) * 32768 + pos) = lb;
}

// ---------------- prep ----------------
__global__ void k_zeroi(int* __restrict__ p, int n) {
    int i = blockIdx.x * blockDim.x + threadIdx.x;
    if (i < n) p[i] = 0;
}

__global__ __launch_bounds__(256) void k_dinv_bsum(const int* __restrict__ deg,
                                                   float* __restrict__ dinv,
                                                   int* __restrict__ bsum) {
    __shared__ int s[256];
    int b = blockIdx.x, t = threadIdx.x;
    int base = b * SCAN_BS + t * 4;
    int v = 0;
#pragma unroll
    for (int j = 0; j < 4; j++) {
        int i = base + j;
        if (i < N_NODES) {
            int d = deg[i];
            dinv[i] = (d > 0) ? rsqrtf((float)d) : 0.f;
            v += d;
        }
    }
    s[t] = v;
    __syncthreads();
    for (int off = 128; off > 0; off >>= 1) {
        if (t < off) s[t] += s[t + off];
        __syncthreads();
    }
    if (t == 0) bsum[b] = s[0];
}

__global__ __launch_bounds__(128) void k_scansums(const int* __restrict__ bsum,
                                                  int* __restrict__ boff,
                                                  int* __restrict__ rowptr) {
    __shared__ int s[128];
    int t = threadIdx.x;
    int v = (t < N_SCAN_BLOCKS) ? bsum[t] : 0;
    s[t] = v;
    __syncthreads();
    for (int off = 1; off < 128; off <<= 1) {
        int u = (t >= off) ? s[t - off] : 0;
        __syncthreads();
        s[t] += u;
        __syncthreads();
    }
    if (t < N_SCAN_BLOCKS) boff[t] = s[t] - v;
    if (t == N_SCAN_BLOCKS - 1) rowptr[N_NODES] = s[t];
}

__global__ __launch_bounds__(SCAN_BS) void k_scanapply(const int* __restrict__ deg,
                                                       const int* __restrict__ boff,
                                                       int* __restrict__ rowptr,
                                                       int* __restrict__ cursor) {
    __shared__ int s[SCAN_BS];
    int b = blockIdx.x, t = threadIdx.x;
    int i = b * SCAN_BS + t;
    int v = (i < N_NODES) ? deg[i] : 0;
    s[t] = v;
    __syncthreads();
    for (int off = 1; off < SCAN_BS; off <<= 1) {
        int u = (t >= off) ? s[t - off] : 0;
        __syncthreads();
        s[t] += u;
        __syncthreads();
    }
    if (i < N_NODES) {
        int excl = boff[b] + s[t] - v;
        rowptr[i] = excl;
        cursor[i] = excl;
    }
}

__global__ void k_fill(const int* __restrict__ ei, const float* __restrict__ dinv,
                       int* __restrict__ cursor, int* __restrict__ esrc,
                       float* __restrict__ enorm) {
    int e = blockIdx.x * blockDim.x + threadIdx.x;
    if (e >= N_EDGES) return;
    int r = ei[e];
    int c = ei[N_EDGES + e];
    int pos = atomicAdd(&cursor[c], 1);
    esrc[pos] = r;
    enorm[pos] = dinv[r] * dinv[c];
}

// ---------------- GEMM common (fp16 A, fp16 hi/lo W; 2-term) ----------------
#define OFF_A  0u
#define OFF_WH 16384u
#define OFF_WL 49152u
#define GEMM_SMEM 81920
#define GEMM_TPB 256

__device__ __forceinline__ uint2 half_pack4(float4 v) {
    __half2 p0 = __floats2half2_rn(v.x, v.y);
    __half2 p1 = __floats2half2_rn(v.z, v.w);
    return make_uint2(*(uint32_t*)&p0, *(uint32_t*)&p1);
}

__device__ __forceinline__ void w_copy_async(uint32_t sb, int tid, int layer) {
    const unsigned char* sh = g_wt + (size_t)(layer * 2 + 0) * 32768;
    const unsigned char* sl = g_wt + (size_t)(layer * 2 + 1) * 32768;
#pragma unroll
    for (int j = 0; j < 8; j++) {
        uint32_t off = (uint32_t)(tid + j * 256) * 16;
        CP_ASYNC16(sb + OFF_WH + off, sh + off);
        CP_ASYNC16(sb + OFF_WL + off, sl + off);
    }
}

// ---------------- X pre-split (layer 0 staging, side stream) ----------------
__global__ void k_xsplit(const float* __restrict__ X) {
    int idx = blockIdx.x * blockDim.x + threadIdx.x;  // float4 index
    if (idx >= N_NODES * 32) return;
    int n = idx >> 5;
    int qp = idx & 31;
    float4 v = ((const float4*)X)[idx];
    uint2 u = half_pack4(v);
    size_t base = (size_t)(n >> 6) * 16384 + swz(n & 63, qp * 8);
    *(uint2*)(g_ahi + base) = u;
}

// ---------------- GEMM: H(fp16) = tiles(g_ahi) @ (W_hi + W_lo) ----------------
__global__ __launch_bounds__(GEMM_TPB, 2) void k_gemm_ps(int layer,
                                                         __half* __restrict__ H) {
    extern __shared__ unsigned char smem[];
    const uint32_t sb = s2u(smem);
    const int tid = threadIdx.x;
    const int w = tid >> 5;
    const int lane = tid & 31;
    const int wm = w >> 2;
    const int wn = w & 3;
    const int row0 = blockIdx.x * M_TILE;

    w_copy_async(sb, tid, layer);
    {
        const unsigned char* ah = g_ahi + (size_t)blockIdx.x * 16384;
#pragma unroll
        for (int j = 0; j < 4; j++) {
            uint32_t off = (uint32_t)(tid + j * 256) * 16;
            CP_ASYNC16(sb + OFF_A + off, ah + off);
        }
    }
    CP_COMMIT();
    CP_WAIT0();
    __syncthreads();

    float acc[2][4][4];
#pragma unroll
    for (int mi = 0; mi < 2; mi++)
#pragma unroll
        for (int ni = 0; ni < 4; ni++)
#pragma unroll
            for (int j = 0; j < 4; j++) acc[mi][ni][j] = 0.f;

    const int a_row = wm * 32 + (lane & 15);
    const int a_kb  = (lane >> 4) << 4;
    const int b_row = wn * 32 + ((lane >> 4) << 3) + (lane & 7);
    const int b_kb  = ((lane >> 3) & 1) << 4;

#pragma unroll
    for (int ks = 0; ks < 8; ks++) {
        uint32_t av[2][4], bh[2][4], bl[2][4];
#pragma unroll
        for (int mi = 0; mi < 2; mi++) {
            uint32_t addr = swz(a_row + mi * 16, a_kb + ks * 32);
            LDSM_X4(av[mi], sb + OFF_A + addr);
        }
#pragma unroll
        for (int p = 0; p < 2; p++) {
            uint32_t addr = swz(b_row + p * 16, b_kb + ks * 32);
            LDSM_X4(bh[p], sb + OFF_WH + addr);
            LDSM_X4(bl[p], sb + OFF_WL + addr);
        }
#pragma unroll
        for (int mi = 0; mi < 2; mi++) {
#pragma unroll
            for (int p = 0; p < 2; p++) {
#pragma unroll
                for (int s = 0; s < 2; s++) {
                    int ni = p * 2 + s;
                    MMA_F16(acc[mi][ni], av[mi], bh[p][s * 2], bh[p][s * 2 + 1]);
                    MMA_F16(acc[mi][ni], av[mi], bl[p][s * 2], bl[p][s * 2 + 1]);
                }
            }
        }
    }

    // epilogue: fp16 H stores
#pragma unroll
    for (int mi = 0; mi < 2; mi++) {
        int r1 = row0 + wm * 32 + mi * 16 + (lane >> 2);
        int r2 = r1 + 8;
#pragma unroll
        for (int ni = 0; ni < 4; ni++) {
            int col = wn * 32 + ni * 8 + 2 * (lane & 3);
            if (r1 < N_NODES)
                *(__half2*)(H + (size_t)r1 * D + col) =
                    __floats2half2_rn(acc[mi][ni][0], acc[mi][ni][1]);
            if (r2 < N_NODES)
                *(__half2*)(H + (size_t)r2 * D + col) =
                    __floats2half2_rn(acc[mi][ni][2], acc[mi][ni][3]);
        }
    }
}

// ---------------- CSR gather over fp16 H ----------------
__device__ __forceinline__ void acc_edge(float4& acc, const __half* __restrict__ H,
                                         int s, float nv, int lane) {
    uint2 raw = __ldg((const uint2*)(H + (size_t)s * D) + lane);
    float2 f0 = __half22float2(*(__half2*)&raw.x);
    float2 f1 = __half22float2(*(__half2*)&raw.y);
    acc.x += f0.x * nv; acc.y += f0.y * nv;
    acc.z += f1.x * nv; acc.w += f1.y * nv;
}

// SPLIT=true: fused bias+relu, quantize to fp16, write swizzled A image.
// SPLIT=false: bias only, write fp32 rows to out.
template <bool SPLIT>
__global__ __launch_bounds__(256) void k_gather(const int* __restrict__ rowptr,
                                                const int* __restrict__ esrc,
                                                const float* __restrict__ enorm,
                                                const __half* __restrict__ H,
                                                const float* __restrict__ bvec,
                                                float* __restrict__ out) {
    int n = blockIdx.x * 8 + (threadIdx.x >> 5);
    if (n >= N_NODES) return;
    int lane = threadIdx.x & 31;

    float4 acc = ((const float4*)bvec)[lane];

    int e = rowptr[n];
    int end = rowptr[n + 1];
    for (; e + 4 <= end; e += 4) {
        int s0 = esrc[e], s1 = esrc[e + 1], s2 = esrc[e + 2], s3 = esrc[e + 3];
        float n0 = enorm[e], n1 = enorm[e + 1], n2 = enorm[e + 2], n3 = enorm[e + 3];
        acc_edge(acc, H, s0, n0, lane);
        acc_edge(acc, H, s1, n1, lane);
        acc_edge(acc, H, s2, n2, lane);
        acc_edge(acc, H, s3, n3, lane);
    }
    for (; e < end; e++) {
        acc_edge(acc, H, esrc[e], enorm[e], lane);
    }

    if (SPLIT) {
        acc.x = fmaxf(acc.x, 0.f); acc.y = fmaxf(acc.y, 0.f);
        acc.z = fmaxf(acc.z, 0.f); acc.w = fmaxf(acc.w, 0.f);
        uint2 u = half_pack4(acc);
        size_t base = (size_t)(n >> 6) * 16384 + swz(n & 63, lane * 8);
        *(uint2*)(g_ahi + base) = u;
    } else {
        ((float4*)(out + (size_t)n * D))[lane] = acc;
    }
}

// ---------------- launch ----------------
extern "C" void kernel_launch(void* const* d_in, const int* in_sizes, int n_in,
                              void* d_out, int out_size) {
    const float* x = (const float*)d_in[0];
    const int* ei_raw = (const int*)d_in[1];
    const float* W = (const float*)d_in[3];
    const float* b = (const float*)d_in[4];
    float* out = (float*)d_out;

    float *dinv, *enorm;
    __half *h, *h2;
    int *deg, *rowptr, *cursor, *bsum, *boff, *esrc, *ei;
    cudaGetSymbolAddress((void**)&dinv, g_dinv);
    cudaGetSymbolAddress((void**)&h, g_h);
    cudaGetSymbolAddress((void**)&h2, g_h2);
    cudaGetSymbolAddress((void**)&enorm, g_enorm);
    cudaGetSymbolAddress((void**)&deg, g_deg);
    cudaGetSymbolAddress((void**)&rowptr, g_rowptr);
    cudaGetSymbolAddress((void**)&cursor, g_cursor);
    cudaGetSymbolAddress((void**)&bsum, g_bsum);
    cudaGetSymbolAddress((void**)&boff, g_boff);
    cudaGetSymbolAddress((void**)&esrc, g_esrc);
    cudaGetSymbolAddress((void**)&ei, g_ei);

    cudaFuncSetAttribute(k_gemm_ps, cudaFuncAttributeMaxDynamicSharedMemorySize, GEMM_SMEM);

    const int TPB = 256;
    const int GATH_BLOCKS = (N_NODES + 7) / 8;

    // fork: wprep + xsplit + gemm0 overlap the edge-prep chain
    cudaStream_t s2;
    cudaEvent_t evFork, evJoin;
    cudaStreamCreateWithFlags(&s2, cudaStreamNonBlocking);
    cudaEventCreateWithFlags(&evFork, cudaEventDisableTiming);
    cudaEventCreateWithFlags(&evJoin, cudaEventDisableTiming);

    cudaEventRecord(evFork, 0);
    cudaStreamWaitEvent(s2, evFork, 0);

    k_wprep<<<(3 * 128 * 128 + TPB - 1) / TPB, TPB, 0, s2>>>(W);
    k_xsplit<<<(N_NODES * 32 + TPB - 1) / TPB, TPB, 0, s2>>>(x);
    k_gemm_ps<<<GEMM_BLOCKS, GEMM_TPB, GEMM_SMEM, s2>>>(0, h);
    cudaEventRecord(evJoin, s2);

    k_zeroi<<<(N_NODES + TPB - 1) / TPB, TPB>>>(deg, N_NODES);
    k_convert_hist<<<(N_EDGES + TPB - 1) / TPB, TPB>>>(ei_raw, ei, deg);
    k_dinv_bsum<<<N_SCAN_BLOCKS, 256>>>(deg, dinv, bsum);
    k_scansums<<<1, 128>>>(bsum, boff, rowptr);
    k_scanapply<<<N_SCAN_BLOCKS, SCAN_BS>>>(deg, boff, rowptr, cursor);
    k_fill<<<(N_EDGES + TPB - 1) / TPB, TPB>>>(ei, dinv, cursor, esrc, enorm);

    cudaStreamWaitEvent(0, evJoin, 0);

    // layer 1: gather(h)+b0+relu -> fp16 A image; GEMM W1 -> h2
    k_gather<true><<<GATH_BLOCKS, TPB>>>(rowptr, esrc, enorm, h, b + 0 * D, nullptr);
    k_gemm_ps<<<GEMM_BLOCKS, GEMM_TPB, GEMM_SMEM>>>(1, h2);
    // layer 2: gather(h2)+b1+relu -> fp16 A image; GEMM W2 -> h
    k_gather<true><<<GATH_BLOCKS, TPB>>>(rowptr, esrc, enorm, h2, b + 1 * D, nullptr);
    k_gemm_ps<<<GEMM_BLOCKS, GEMM_TPB, GEMM_SMEM>>>(2, h);
    // final: gather(h)+b2 -> out (fp32)
    k_gather<false><<<GATH_BLOCKS, TPB>>>(rowptr, esrc, enorm, h, b + 2 * D, out);
}

// round 13
// speedup vs baseline: 1.4806x; 1.0043x over previous
#include <cuda_runtime.h>
#include <cuda_fp16.h>
#include <cstdint>

#define N_NODES 100000
#define N_EDGES 640000
#define E_PAD 1048576   // >= N_EDGES + 3*N_NODES
#define D 128
#define SCAN_BS 1024
#define N_SCAN_BLOCKS ((N_NODES + SCAN_BS - 1) / SCAN_BS)  // 98
#define M_TILE 64
#define GEMM_BLOCKS ((N_NODES + M_TILE - 1) / M_TILE)      // 1563

// ---- scratch ----
__device__ __half g_h[(size_t)N_NODES * D];
__device__ __half g_h2[(size_t)N_NODES * D];
// pre-swizzled fp16 A-tile images: [tile][64 rows][256B] = 16KB/tile
__device__ unsigned char g_ahi[(size_t)GEMM_BLOCKS * 16384];
__device__ int   g_deg[N_NODES];
__device__ float g_dinv[N_NODES];
__device__ int   g_rowptr[N_NODES + 1];
__device__ int   g_cursor[N_NODES];
__device__ int   g_bsum[128];
__device__ int   g_boff[128];
__device__ int   g_esrc[E_PAD];
__device__ float g_enorm[E_PAD];
__device__ int   g_ei[2 * N_EDGES];
// W transposed, fp16 hi/lo split, pre-swizzled: [layer][hi|lo] 32KB each
__device__ unsigned char g_wt[3 * 2 * 32768];

__device__ __forceinline__ uint32_t swz(int row, int kb) {
    return (uint32_t)(row * 256 + (kb ^ ((row & 7) << 4)));
}

__device__ __forceinline__ uint32_t s2u(const void* p) {
    uint32_t a;
    asm("{ .reg .u64 t; cvta.to.shared.u64 t, %1; cvt.u32.u64 %0, t; }"
        : "=r"(a) : "l"(p));
    return a;
}

#define LDSM_X4(d, a) \
    asm volatile("ldmatrix.sync.aligned.m8n8.x4.shared.b16 {%0,%1,%2,%3}, [%4];" \
        : "=r"((d)[0]), "=r"((d)[1]), "=r"((d)[2]), "=r"((d)[3]) : "r"(a))

#define MMA_F16(c, a, b0, b1) \
    asm volatile("mma.sync.aligned.m16n8k16.row.col.f32.f16.f16.f32 " \
        "{%0,%1,%2,%3}, {%4,%5,%6,%7}, {%8,%9}, {%0,%1,%2,%3};" \
        : "+f"((c)[0]), "+f"((c)[1]), "+f"((c)[2]), "+f"((c)[3]) \
        : "r"((a)[0]), "r"((a)[1]), "r"((a)[2]), "r"((a)[3]), "r"(b0), "r"(b1))

#define CP_ASYNC16(dst, src) \
    asm volatile("cp.async.ca.shared.global [%0], [%1], 16;" :: "r"(dst), "l"(src))
#define CP_COMMIT() asm volatile("cp.async.commit_group;")
#define CP_WAIT0()  asm volatile("cp.async.wait_group 0;")

__device__ __forceinline__ int pad4(int d) { return (d + 3) & ~3; }

// ---------------- edge-index dtype sniff ----------------
__device__ __forceinline__ bool ei_is_int64(const int* __restrict__ w) {
    bool z = true;
#pragma unroll
    for (int i = 1; i < 32; i += 2) z &= (w[i] == 0);
    return z;
}

__global__ void k_convert_hist(const int* __restrict__ ei_raw, int* __restrict__ ei32,
                               int* __restrict__ deg) {
    int e = blockIdx.x * blockDim.x + threadIdx.x;
    if (e >= N_EDGES) return;
    bool is64 = ei_is_int64(ei_raw);
    int r = is64 ? ei_raw[2 * e] : ei_raw[e];
    int c = is64 ? ei_raw[2 * (N_EDGES + e)] : ei_raw[N_EDGES + e];
    ei32[e] = r;
    ei32[N_EDGES + e] = c;
    atomicAdd(&deg[c], 1);
}

// ---------------- W prep: transpose + fp16 hi/lo split + swizzle ----------------
__global__ void k_wprep(const float* __restrict__ W) {
    int i = blockIdx.x * blockDim.x + threadIdx.x;
    if (i >= 3 * 128 * 128) return;
    int l = i >> 14;
    int rem = i & 16383;
    int k = rem >> 7;
    int n = rem & 127;
    float w = W[l * 16384 + k * 128 + n];
    __half hb = __float2half_rn(w);
    __half lb = __float2half_rn(w - __half2float(hb));
    uint32_t pos = swz(n, k * 2);
    *(__half*)(g_wt + (size_t)(l * 2 + 0) * 32768 + pos) = hb;
    *(__half*)(g_wt + (size_t)(l * 2 + 1) * 32768 + pos) = lb;
}

// ---------------- prep (padded CSR) ----------------
__global__ __launch_bounds__(256) void k_dinv_bsum(const int* __restrict__ deg,
                                                   float* __restrict__ dinv,
                                                   int* __restrict__ bsum) {
    __shared__ int s[256];
    int b = blockIdx.x, t = threadIdx.x;
    int base = b * SCAN_BS + t * 4;
    int v = 0;
#pragma unroll
    for (int j = 0; j < 4; j++) {
        int i = base + j;
        if (i < N_NODES) {
            int d = deg[i];
            dinv[i] = (d > 0) ? rsqrtf((float)d) : 0.f;
            v += pad4(d);
        }
    }
    s[t] = v;
    __syncthreads();
    for (int off = 128; off > 0; off >>= 1) {
        if (t < off) s[t] += s[t + off];
        __syncthreads();
    }
    if (t == 0) bsum[b] = s[0];
}

__global__ __launch_bounds__(128) void k_scansums(const int* __restrict__ bsum,
                                                  int* __restrict__ boff,
                                                  int* __restrict__ rowptr) {
    __shared__ int s[128];
    int t = threadIdx.x;
    int v = (t < N_SCAN_BLOCKS) ? bsum[t] : 0;
    s[t] = v;
    __syncthreads();
    for (int off = 1; off < 128; off <<= 1) {
        int u = (t >= off) ? s[t - off] : 0;
        __syncthreads();
        s[t] += u;
        __syncthreads();
    }
    if (t < N_SCAN_BLOCKS) boff[t] = s[t] - v;
    if (t == N_SCAN_BLOCKS - 1) rowptr[N_NODES] = s[t];
}

__global__ __launch_bounds__(SCAN_BS) void k_scanapply(const int* __restrict__ deg,
                                                       const int* __restrict__ boff,
                                                       int* __restrict__ rowptr,
                                                       int* __restrict__ cursor) {
    __shared__ int s[SCAN_BS];
    int b = blockIdx.x, t = threadIdx.x;
    int i = b * SCAN_BS + t;
    int v = (i < N_NODES) ? pad4(deg[i]) : 0;
    s[t] = v;
    __syncthreads();
    for (int off = 1; off < SCAN_BS; off <<= 1) {
        int u = (t >= off) ? s[t - off] : 0;
        __syncthreads();
        s[t] += u;
        __syncthreads();
    }
    if (i < N_NODES) {
        int excl = boff[b] + s[t] - v;
        rowptr[i] = excl;
        cursor[i] = excl;
    }
}

__global__ void k_fill(const int* __restrict__ ei, const float* __restrict__ dinv,
                       int* __restrict__ cursor, int* __restrict__ esrc,
                       float* __restrict__ enorm) {
    int e = blockIdx.x * blockDim.x + threadIdx.x;
    if (e >= N_EDGES) return;
    int r = ei[e];
    int c = ei[N_EDGES + e];
    int pos = atomicAdd(&cursor[c], 1);
    esrc[pos] = r;
    enorm[pos] = dinv[r] * dinv[c];
}

// ---------------- GEMM common (fp16 A, fp16 hi/lo W; 2-term) ----------------
#define OFF_A  0u
#define OFF_WH 16384u
#define OFF_WL 49152u
#define GEMM_SMEM 81920
#define GEMM_TPB 256

__device__ __forceinline__ uint2 half_pack4(float4 v) {
    __half2 p0 = __floats2half2_rn(v.x, v.y);
    __half2 p1 = __floats2half2_rn(v.z, v.w);
    return make_uint2(*(uint32_t*)&p0, *(uint32_t*)&p1);
}

__device__ __forceinline__ void w_copy_async(uint32_t sb, int tid, int layer) {
    const unsigned char* sh = g_wt + (size_t)(layer * 2 + 0) * 32768;
    const unsigned char* sl = g_wt + (size_t)(layer * 2 + 1) * 32768;
#pragma unroll
    for (int j = 0; j < 8; j++) {
        uint32_t off = (uint32_t)(tid + j * 256) * 16;
        CP_ASYNC16(sb + OFF_WH + off, sh + off);
        CP_ASYNC16(sb + OFF_WL + off, sl + off);
    }
}

// shared mainloop + fp16 epilogue
__device__ __forceinline__ void mma_main_epi(uint32_t sb, int tid, int row0,
                                             __half* __restrict__ H) {
    const int w = tid >> 5;
    const int lane = tid & 31;
    const int wm = w >> 2;
    const int wn = w & 3;

    float acc[2][4][4];
#pragma unroll
    for (int mi = 0; mi < 2; mi++)
#pragma unroll
        for (int ni = 0; ni < 4; ni++)
#pragma unroll
            for (int j = 0; j < 4; j++) acc[mi][ni][j] = 0.f;

    const int a_row = wm * 32 + (lane & 15);
    const int a_kb  = (lane >> 4) << 4;
    const int b_row = wn * 32 + ((lane >> 4) << 3) + (lane & 7);
    const int b_kb  = ((lane >> 3) & 1) << 4;

#pragma unroll
    for (int ks = 0; ks < 8; ks++) {
        uint32_t av[2][4], bh[2][4], bl[2][4];
#pragma unroll
        for (int mi = 0; mi < 2; mi++) {
            uint32_t addr = swz(a_row + mi * 16, a_kb + ks * 32);
            LDSM_X4(av[mi], sb + OFF_A + addr);
        }
#pragma unroll
        for (int p = 0; p < 2; p++) {
            uint32_t addr = swz(b_row + p * 16, b_kb + ks * 32);
            LDSM_X4(bh[p], sb + OFF_WH + addr);
            LDSM_X4(bl[p], sb + OFF_WL + addr);
        }
#pragma unroll
        for (int mi = 0; mi < 2; mi++) {
#pragma unroll
            for (int p = 0; p < 2; p++) {
#pragma unroll
                for (int s = 0; s < 2; s++) {
                    int ni = p * 2 + s;
                    MMA_F16(acc[mi][ni], av[mi], bh[p][s * 2], bh[p][s * 2 + 1]);
                    MMA_F16(acc[mi][ni], av[mi], bl[p][s * 2], bl[p][s * 2 + 1]);
                }
            }
        }
    }

#pragma unroll
    for (int mi = 0; mi < 2; mi++) {
        int r1 = row0 + wm * 32 + mi * 16 + (lane >> 2);
        int r2 = r1 + 8;
#pragma unroll
        for (int ni = 0; ni < 4; ni++) {
            int col = wn * 32 + ni * 8 + 2 * (lane & 3);
            if (r1 < N_NODES)
                *(__half2*)(H + (size_t)r1 * D + col) =
                    __floats2half2_rn(acc[mi][ni][0], acc[mi][ni][1]);
            if (r2 < N_NODES)
                *(__half2*)(H + (size_t)r2 * D + col) =
                    __floats2half2_rn(acc[mi][ni][2], acc[mi][ni][3]);
        }
    }
}

// ---------------- dense GEMM (layer 0): inline X->fp16 staging ----------------
__global__ __launch_bounds__(GEMM_TPB, 2) void k_gemm_d(const float* __restrict__ X,
                                                        __half* __restrict__ H) {
    extern __shared__ unsigned char smem[];
    const uint32_t sb = s2u(smem);
    const int tid = threadIdx.x;
    const int row0 = blockIdx.x * M_TILE;

    w_copy_async(sb, tid, 0);
    CP_COMMIT();

    {
        int r = tid >> 2;
        int q = tid & 3;
        int gr = row0 + r;
        bool valid = gr < N_NODES;
        const float4* src = (const float4*)(X + (size_t)gr * D);
#pragma unroll
        for (int j = 0; j < 8; j++) {
            int qp = q + j * 4;
            float4 v = valid ? src[qp] : make_float4(0.f, 0.f, 0.f, 0.f);
            uint2 u = half_pack4(v);
            *(uint2*)(smem + OFF_A + swz(r, qp * 8)) = u;
        }
    }
    CP_WAIT0();
    __syncthreads();
    mma_main_epi(sb, tid, row0, H);
}

// ---------------- pre-staged GEMM (layers 1,2) ----------------
__global__ __launch_bounds__(GEMM_TPB, 2) void k_gemm_ps(int layer,
                                                         __half* __restrict__ H) {
    extern __shared__ unsigned char smem[];
    const uint32_t sb = s2u(smem);
    const int tid = threadIdx.x;
    const int row0 = blockIdx.x * M_TILE;

    w_copy_async(sb, tid, layer);
    {
        const unsigned char* ah = g_ahi + (size_t)blockIdx.x * 16384;
#pragma unroll
        for (int j = 0; j < 4; j++) {
            uint32_t off = (uint32_t)(tid + j * 256) * 16;
            CP_ASYNC16(sb + OFF_A + off, ah + off);
        }
    }
    CP_COMMIT();
    CP_WAIT0();
    __syncthreads();
    mma_main_epi(sb, tid, row0, H);
}

// ---------------- padded CSR gather over fp16 H (no tail loop) ----------------
__device__ __forceinline__ void acc_edge(float4& acc, const __half* __restrict__ H,
                                         int s, float nv, int lane) {
    uint2 raw = __ldg((const uint2*)(H + (size_t)s * D) + lane);
    float2 f0 = __half22float2(*(__half2*)&raw.x);
    float2 f1 = __half22float2(*(__half2*)&raw.y);
    acc.x += f0.x * nv; acc.y += f0.y * nv;
    acc.z += f1.x * nv; acc.w += f1.y * nv;
}

// SPLIT=true: fused bias+relu, quantize to fp16, write swizzled A image.
// SPLIT=false: bias only, write fp32 rows to out.
template <bool SPLIT>
__global__ __launch_bounds__(256) void k_gather(const int* __restrict__ rowptr,
                                                const int* __restrict__ esrc,
                                                const float* __restrict__ enorm,
                                                const __half* __restrict__ H,
                                                const float* __restrict__ bvec,
                                                float* __restrict__ out) {
    int n = blockIdx.x * 8 + (threadIdx.x >> 5);
    if (n >= N_NODES) return;
    int lane = threadIdx.x & 31;

    float4 acc = ((const float4*)bvec)[lane];

    int e = rowptr[n];
    int end = rowptr[n + 1];   // always multiple of 4 edges (padded)
    for (; e < end; e += 4) {
        int s0 = esrc[e], s1 = esrc[e + 1], s2 = esrc[e + 2], s3 = esrc[e + 3];
        float n0 = enorm[e], n1 = enorm[e + 1], n2 = enorm[e + 2], n3 = enorm[e + 3];
        acc_edge(acc, H, s0, n0, lane);
        acc_edge(acc, H, s1, n1, lane);
        acc_edge(acc, H, s2, n2, lane);
        acc_edge(acc, H, s3, n3, lane);
    }

    if (SPLIT) {
        acc.x = fmaxf(acc.x, 0.f); acc.y = fmaxf(acc.y, 0.f);
        acc.z = fmaxf(acc.z, 0.f); acc.w = fmaxf(acc.w, 0.f);
        uint2 u = half_pack4(acc);
        size_t base = (size_t)(n >> 6) * 16384 + swz(n & 63, lane * 8);
        *(uint2*)(g_ahi + base) = u;
    } else {
        ((float4*)(out + (size_t)n * D))[lane] = acc;
    }
}

// ---------------- launch ----------------
extern "C" void kernel_launch(void* const* d_in, const int* in_sizes, int n_in,
                              void* d_out, int out_size) {
    const float* x = (const float*)d_in[0];
    const int* ei_raw = (const int*)d_in[1];
    const float* W = (const float*)d_in[3];
    const float* b = (const float*)d_in[4];
    float* out = (float*)d_out;

    float *dinv, *enorm;
    __half *h, *h2;
    int *deg, *rowptr, *cursor, *bsum, *boff, *esrc, *ei;
    cudaGetSymbolAddress((void**)&dinv, g_dinv);
    cudaGetSymbolAddress((void**)&h, g_h);
    cudaGetSymbolAddress((void**)&h2, g_h2);
    cudaGetSymbolAddress((void**)&enorm, g_enorm);
    cudaGetSymbolAddress((void**)&deg, g_deg);
    cudaGetSymbolAddress((void**)&rowptr, g_rowptr);
    cudaGetSymbolAddress((void**)&cursor, g_cursor);
    cudaGetSymbolAddress((void**)&bsum, g_bsum);
    cudaGetSymbolAddress((void**)&boff, g_boff);
    cudaGetSymbolAddress((void**)&esrc, g_esrc);
    cudaGetSymbolAddress((void**)&ei, g_ei);

    cudaFuncSetAttribute(k_gemm_d, cudaFuncAttributeMaxDynamicSharedMemorySize, GEMM_SMEM);
    cudaFuncSetAttribute(k_gemm_ps, cudaFuncAttributeMaxDynamicSharedMemorySize, GEMM_SMEM);

    const int TPB = 256;
    const int GATH_BLOCKS = (N_NODES + 7) / 8;

    // fork: wprep + dense gemm0 overlap the edge-prep chain
    cudaStream_t s2;
    cudaEvent_t evFork, evJoin;
    cudaStreamCreateWithFlags(&s2, cudaStreamNonBlocking);
    cudaEventCreateWithFlags(&evFork, cudaEventDisableTiming);
    cudaEventCreateWithFlags(&evJoin, cudaEventDisableTiming);

    cudaEventRecord(evFork, 0);
    cudaStreamWaitEvent(s2, evFork, 0);

    k_wprep<<<(3 * 128 * 128 + TPB - 1) / TPB, TPB, 0, s2>>>(W);
    k_gemm_d<<<GEMM_BLOCKS, GEMM_TPB, GEMM_SMEM, s2>>>(x, h);
    cudaEventRecord(evJoin, s2);

    // main: edge-prep chain (padded CSR)
    cudaMemsetAsync(deg, 0, N_NODES * sizeof(int), 0);
    cudaMemsetAsync(esrc, 0, E_PAD * sizeof(int), 0);
    cudaMemsetAsync(enorm, 0, E_PAD * sizeof(float), 0);
    k_convert_hist<<<(N_EDGES + TPB - 1) / TPB, TPB>>>(ei_raw, ei, deg);
    k_dinv_bsum<<<N_SCAN_BLOCKS, 256>>>(deg, dinv, bsum);
    k_scansums<<<1, 128>>>(bsum, boff, rowptr);
    k_scanapply<<<N_SCAN_BLOCKS, SCAN_BS>>>(deg, boff, rowptr, cursor);
    k_fill<<<(N_EDGES + TPB - 1) / TPB, TPB>>>(ei, dinv, cursor, esrc, enorm);

    cudaStreamWaitEvent(0, evJoin, 0);

    // layer 1: gather(h)+b0+relu -> fp16 A image; GEMM W1 -> h2
    k_gather<true><<<GATH_BLOCKS, TPB>>>(rowptr, esrc, enorm, h, b + 0 * D, nullptr);
    k_gemm_ps<<<GEMM_BLOCKS, GEMM_TPB, GEMM_SMEM>>>(1, h2);
    // layer 2: gather(h2)+b1+relu -> fp16 A image; GEMM W2 -> h
    k_gather<true><<<GATH_BLOCKS, TPB>>>(rowptr, esrc, enorm, h2, b + 1 * D, nullptr);
    k_gemm_ps<<<GEMM_BLOCKS, GEMM_TPB, GEMM_SMEM>>>(2, h);
    // final: gather(h)+b2 -> out (fp32)
    k_gather<false><<<GATH_BLOCKS, TPB>>>(rowptr, esrc, enorm, h, b + 2 * D, out);
}